// round 7
// baseline (speedup 1.0000x reference)
#include <cuda_runtime.h>
#include <cuda_bf16.h>
#include <cstdint>

#define NP 100      // proxies
#define NS 1024     // samples
#define NN 1124     // total nodes
#define MPAD 1152   // NN padded to 128
#define D  512
#define KPAD 112    // NP padded to multiple of 16
#define SPLITK 8    // split-K parts for proxy aggregation

// scratch (device globals; no allocation allowed)
__device__ float g_HW[NN * D];
__device__ float g_lsrc[NN];
__device__ float g_ldst[NN];
__device__ float g_alphaS[NS * KPAD];
__device__ float g_aselfS[NS];
__device__ float g_alphaP[NP * NS];
__device__ float g_aselfP[NP];
__device__ float g_ppart[SPLITK * NP * D];
__device__ float g_v[4][D];             // W1@as1, W1@ad1, W2@as2, W2@ad2
__device__ float g_lp[8][NN][2];        // layer-2 logit partials [ntile][node][src/dst]
// bf16 split operands for tensor-core GEMMs
__device__ __nv_bfloat16 g_Ah[MPAD * D];
__device__ __nv_bfloat16 g_Al[MPAD * D];
__device__ __nv_bfloat16 g_W1h[D * D];  // transposed [N,K]
__device__ __nv_bfloat16 g_W1l[D * D];
__device__ __nv_bfloat16 g_W2h[D * D];
__device__ __nv_bfloat16 g_W2l[D * D];
__device__ __nv_bfloat16 g_FCh[128 * D]; // fc_w transposed [100->128, 512]
__device__ __nv_bfloat16 g_FCl[128 * D];

__device__ __forceinline__ float lrelu(float v) { return v > 0.f ? v : 0.2f * v; }

__device__ __forceinline__ uint32_t smem_u32(const void* p) {
    uint32_t a;
    asm("{ .reg .u64 t; cvta.to.shared.u64 t, %1; cvt.u32.u64 %0, t; }" : "=r"(a) : "l"(p));
    return a;
}

// ============================ prep ============================
// grid (16,16,4): z=0 W1 transpose/split, z=1 W2, z=2 matvecs, z=3 fcw transpose/split
__global__ void k_prep(const float* __restrict__ W1, const float* __restrict__ W2,
                       const float* __restrict__ fcw,
                       const float* __restrict__ as1, const float* __restrict__ ad1,
                       const float* __restrict__ as2, const float* __restrict__ ad2) {
    if (blockIdx.z < 2) {
        const float* W = blockIdx.z ? W2 : W1;
        __nv_bfloat16* Wh = blockIdx.z ? g_W2h : g_W1h;
        __nv_bfloat16* Wl = blockIdx.z ? g_W2l : g_W1l;
        __shared__ float t[32][33];
        int tx = threadIdx.x & 31, ty = threadIdx.x >> 5;
        int k0 = blockIdx.y * 32, n0 = blockIdx.x * 32;
        #pragma unroll
        for (int j = 0; j < 4; j++)
            t[ty + 8 * j][tx] = W[(size_t)(k0 + ty + 8 * j) * D + n0 + tx];
        __syncthreads();
        #pragma unroll
        for (int j = 0; j < 4; j++) {
            int n = n0 + ty + 8 * j, k = k0 + tx;
            float v = t[tx][ty + 8 * j];
            __nv_bfloat16 hi = __float2bfloat16(v);
            Wh[(size_t)n * D + k] = hi;
            Wl[(size_t)n * D + k] = __float2bfloat16(v - __bfloat162float(hi));
        }
    } else if (blockIdx.z == 2) {
        // 4 matvecs W@a: 2048 warps
        int b = blockIdx.y * 16 + blockIdx.x;
        int gw = b * 8 + (threadIdx.x >> 5);
        int lane = threadIdx.x & 31;
        int vec = gw >> 9, k = gw & 511;
        const float* W = (vec < 2) ? W1 : W2;
        const float* a = (vec == 0) ? as1 : (vec == 1) ? ad1 : (vec == 2) ? as2 : ad2;
        const float* wr = W + (size_t)k * D;
        float s = 0.f;
        #pragma unroll 4
        for (int n = lane; n < D; n += 32) s += wr[n] * a[n];
        #pragma unroll
        for (int o = 16; o > 0; o >>= 1) s += __shfl_xor_sync(0xffffffffu, s, o);
        if (lane == 0) g_v[vec][k] = s;
    } else {
        // fcw [512,100] -> [128,512] transposed split (rows >= 100 zero)
        if (blockIdx.x >= 4) return;
        __shared__ float t[32][33];
        int tx = threadIdx.x & 31, ty = threadIdx.x >> 5;
        int k0 = blockIdx.y * 32, n0 = blockIdx.x * 32;
        #pragma unroll
        for (int j = 0; j < 4; j++) {
            int n = n0 + tx;
            t[ty + 8 * j][tx] = (n < 100) ? fcw[(size_t)(k0 + ty + 8 * j) * 100 + n] : 0.f;
        }
        __syncthreads();
        #pragma unroll
        for (int j = 0; j < 4; j++) {
            int n = n0 + ty + 8 * j, k = k0 + tx;
            float v = t[tx][ty + 8 * j];
            __nv_bfloat16 hi = __float2bfloat16(v);
            g_FCh[(size_t)n * D + k] = hi;
            g_FCl[(size_t)n * D + k] = __float2bfloat16(v - __bfloat162float(hi));
        }
    }
}

// ============================ layer-1 convert + logits ============================
__global__ void k_cvt_log(const float* __restrict__ x, const float* __restrict__ prox) {
    __shared__ float sh[8];
    int row = blockIdx.x, tid = threadIdx.x;
    int base = row * D + tid * 4;

    float4 v = make_float4(0.f, 0.f, 0.f, 0.f);
    if (row < NP)      v = *reinterpret_cast<const float4*>(prox + base);
    else if (row < NN) v = *reinterpret_cast<const float4*>(x + base - NP * D);

    __nv_bfloat16 h0 = __float2bfloat16(v.x), h1 = __float2bfloat16(v.y);
    __nv_bfloat16 h2 = __float2bfloat16(v.z), h3 = __float2bfloat16(v.w);
    *reinterpret_cast<__nv_bfloat162*>(g_Ah + base)     = __nv_bfloat162(h0, h1);
    *reinterpret_cast<__nv_bfloat162*>(g_Ah + base + 2) = __nv_bfloat162(h2, h3);
    *reinterpret_cast<__nv_bfloat162*>(g_Al + base) =
        __nv_bfloat162(__float2bfloat16(v.x - __bfloat162float(h0)),
                       __float2bfloat16(v.y - __bfloat162float(h1)));
    *reinterpret_cast<__nv_bfloat162*>(g_Al + base + 2) =
        __nv_bfloat162(__float2bfloat16(v.z - __bfloat162float(h2)),
                       __float2bfloat16(v.w - __bfloat162float(h3)));

    if (row >= NN) return;

    float4 vs = *reinterpret_cast<const float4*>(&g_v[0][tid * 4]);
    float4 vd = *reinterpret_cast<const float4*>(&g_v[1][tid * 4]);
    float s = v.x * vs.x + v.y * vs.y + v.z * vs.z + v.w * vs.w;
    float t = v.x * vd.x + v.y * vd.y + v.z * vd.z + v.w * vd.w;
    #pragma unroll
    for (int o = 16; o > 0; o >>= 1) {
        s += __shfl_xor_sync(0xffffffffu, s, o);
        t += __shfl_xor_sync(0xffffffffu, t, o);
    }
    if ((tid & 31) == 0) { sh[tid >> 5] = s; sh[4 + (tid >> 5)] = t; }
    __syncthreads();
    if (tid == 0) g_lsrc[row] = sh[0] + sh[1] + sh[2] + sh[3];
    if (tid == 32) g_ldst[row] = sh[4] + sh[5] + sh[6] + sh[7];
}

// ============================ alpha device blocks ============================
// layer-1 alpha: b in 0..227 (0..127 samples, 128..227 proxies). no max subtraction.
__device__ void alpha1_block(int b, const float* __restrict__ lsrc,
                             const float* __restrict__ ldst) {
    int tid = threadIdx.x;
    if (b < 128) {
        int warp = b * 8 + (tid >> 5);
        int lane = tid & 31;
        int node = NP + warp;
        float ld = ldst[node];
        float w[4], sum = 0.f;
        #pragma unroll
        for (int i = 0; i < 4; i++) {
            int p = lane + 32 * i;
            w[i] = (p < NP) ? __expf(lrelu(lsrc[p] + ld)) : 0.f;
            sum += w[i];
        }
        float wself = __expf(lrelu(lsrc[node] + ld));
        #pragma unroll
        for (int o = 16; o > 0; o >>= 1) sum += __shfl_xor_sync(0xffffffffu, sum, o);
        float inv = 1.f / (sum + wself);
        #pragma unroll
        for (int i = 0; i < 4; i++) {
            int p = lane + 32 * i;
            if (p < KPAD) g_alphaS[(size_t)warp * KPAD + p] = w[i] * inv;
        }
        if (lane == 0) g_aselfS[warp] = wself * inv;
    } else {
        __shared__ float sh[8];
        __shared__ float s_inv;
        int p = b - 128;
        float ld = ldst[p];
        float w[4], sum = 0.f;
        #pragma unroll
        for (int i = 0; i < 4; i++) {
            w[i] = __expf(lrelu(lsrc[NP + tid + i * 256] + ld));
            sum += w[i];
        }
        float wself = __expf(lrelu(lsrc[p] + ld));
        #pragma unroll
        for (int o = 16; o > 0; o >>= 1) sum += __shfl_xor_sync(0xffffffffu, sum, o);
        if ((tid & 31) == 0) sh[tid >> 5] = sum;
        __syncthreads();
        if (tid == 0) {
            float ss = 0.f;
            #pragma unroll
            for (int i = 0; i < 8; i++) ss += sh[i];
            s_inv = 1.f / (ss + wself);
        }
        __syncthreads();
        float inv = s_inv;
        #pragma unroll
        for (int i = 0; i < 4; i++)
            g_alphaP[(size_t)p * NS + tid + i * 256] = w[i] * inv;
        if (tid == 0) g_aselfP[p] = wself * inv;
    }
}

// layer-2 alpha (samples only) from g_lp partials; b in 0..127
__device__ void alpha2_block(int b) {
    int warp = b * 8 + (threadIdx.x >> 5);
    int lane = threadIdx.x & 31;
    int node = NP + warp;
    float lsn = 0.f, ldn = 0.f;
    #pragma unroll
    for (int ti = 0; ti < 8; ti++) {
        lsn += g_lp[ti][node][0];
        ldn += g_lp[ti][node][1];
    }
    float w[4], sum = 0.f;
    #pragma unroll
    for (int i = 0; i < 4; i++) {
        int p = lane + 32 * i;
        if (p < NP) {
            float lsp = g_lp[0][p][0] + g_lp[1][p][0];
            w[i] = __expf(lrelu(lsp + ldn));
        } else w[i] = 0.f;
        sum += w[i];
    }
    float wself = __expf(lrelu(lsn + ldn));
    #pragma unroll
    for (int o = 16; o > 0; o >>= 1) sum += __shfl_xor_sync(0xffffffffu, sum, o);
    float inv = 1.f / (sum + wself);
    #pragma unroll
    for (int i = 0; i < 4; i++) {
        int p = lane + 32 * i;
        if (p < KPAD) g_alphaS[(size_t)warp * KPAD + p] = w[i] * inv;
    }
    if (lane == 0) g_aselfS[warp] = wself * inv;
}

// ============================ generic bf16-split tensor-core GEMM ============================
// 64x64 tile, 8 warps (2m x 4n), BK=64, cp.async double-buffered. K fixed = 512.
// blocks with blockIdx.y >= my run alpha blocks instead (mode 1: layer1, 2: layer2).
#define SWB(r, b) ((r) * 128 + ((b) ^ (((r) & 7) << 4)))
#define STAGE_BYTES 32768

__device__ __forceinline__ void ldm_x4(uint32_t* f, uint32_t addr) {
    asm volatile("ldmatrix.sync.aligned.m8n8.x4.shared.b16 {%0,%1,%2,%3}, [%4];"
                 : "=r"(f[0]), "=r"(f[1]), "=r"(f[2]), "=r"(f[3]) : "r"(addr));
}
__device__ __forceinline__ void ldm_x2(uint32_t* f, uint32_t addr) {
    asm volatile("ldmatrix.sync.aligned.m8n8.x2.shared.b16 {%0,%1}, [%2];"
                 : "=r"(f[0]), "=r"(f[1]) : "r"(addr));
}
__device__ __forceinline__ void mma_bf16(float* c, const uint32_t* a, const uint32_t* b) {
    asm volatile(
        "mma.sync.aligned.m16n8k16.row.col.f32.bf16.bf16.f32 "
        "{%0,%1,%2,%3}, {%4,%5,%6,%7}, {%8,%9}, {%0,%1,%2,%3};"
        : "+f"(c[0]), "+f"(c[1]), "+f"(c[2]), "+f"(c[3])
        : "r"(a[0]), "r"(a[1]), "r"(a[2]), "r"(a[3]), "r"(b[0]), "r"(b[1]));
}
__device__ __forceinline__ void cpa16(uint32_t saddr, const void* g) {
    asm volatile("cp.async.cg.shared.global [%0], [%1], 16;" :: "r"(saddr), "l"(g));
}

__global__ void __launch_bounds__(256, 1) k_mma(
    const __nv_bfloat16* __restrict__ Ah, const __nv_bfloat16* __restrict__ Al,
    const __nv_bfloat16* __restrict__ Bh, const __nv_bfloat16* __restrict__ Bl,
    float* __restrict__ C, int ldc, int rmax, int cmax, const float* __restrict__ bias,
    int my, int alpha_mode, const float* __restrict__ lsrc, const float* __restrict__ ldst) {
    extern __shared__ __align__(16) char sm[];   // 2 x 32KB stages
    if ((int)blockIdx.y >= my) {
        int b = ((int)blockIdx.y - my) * 8 + (int)blockIdx.x;
        if (alpha_mode == 1) { if (b < 228) alpha1_block(b, lsrc, ldst); }
        else                 { if (b < 128) alpha2_block(b); }
        return;
    }
    int tid = threadIdx.x, wid = tid >> 5, lane = tid & 31;
    int n0 = blockIdx.x * 64, m0 = blockIdx.y * 64;
    int wm = (wid >> 2) * 32, wn = (wid & 3) * 16;
    uint32_t sb = smem_u32(sm);

    int li = tid * 2;
    int lr0 = li >> 3, ls0 = li & 7;
    int lr1 = (li + 1) >> 3, ls1 = (li + 1) & 7;

    int a_r = (lane & 7) + ((lane >> 3) & 1) * 8;
    int a_kb = (lane >> 4) * 16;
    int b_r = lane & 7;
    int b_kb = ((lane >> 3) & 1) * 16;

    float acc[2][2][4] = {};

    const __nv_bfloat16* srcs[4] = { Ah, Al, Bh, Bl };
    int rbases[4] = { m0, m0, n0, n0 };

    auto issue = [&](int c, int st) {
        int kc = c * 64;
        uint32_t stb = sb + st * STAGE_BYTES;
        #pragma unroll
        for (int o = 0; o < 4; o++) {
            const __nv_bfloat16* s = srcs[o];
            int rb = rbases[o];
            cpa16(stb + o * 8192 + SWB(lr0, ls0 * 16), s + (size_t)(rb + lr0) * D + kc + ls0 * 8);
            cpa16(stb + o * 8192 + SWB(lr1, ls1 * 16), s + (size_t)(rb + lr1) * D + kc + ls1 * 8);
        }
        asm volatile("cp.async.commit_group;");
    };

    issue(0, 0);
    asm volatile("cp.async.wait_group 0;");
    __syncthreads();

    for (int c = 0; c < 8; c++) {
        int st = c & 1;
        if (c < 7) issue(c + 1, st ^ 1);
        uint32_t stb = sb + st * STAGE_BYTES;

        #pragma unroll
        for (int ks = 0; ks < 4; ks++) {
            int kb = ks * 32;
            uint32_t ah[2][4], al[2][4], bh[2][2], bl[2][2];
            #pragma unroll
            for (int mt = 0; mt < 2; mt++) {
                int r = wm + mt * 16 + a_r;
                ldm_x4(ah[mt], stb + 0    + SWB(r, kb + a_kb));
                ldm_x4(al[mt], stb + 8192 + SWB(r, kb + a_kb));
            }
            #pragma unroll
            for (int nt = 0; nt < 2; nt++) {
                int r = wn + nt * 8 + b_r;
                ldm_x2(bh[nt], stb + 16384 + SWB(r, kb + b_kb));
                ldm_x2(bl[nt], stb + 24576 + SWB(r, kb + b_kb));
            }
            #pragma unroll
            for (int mt = 0; mt < 2; mt++)
                #pragma unroll
                for (int nt = 0; nt < 2; nt++) {
                    mma_bf16(acc[mt][nt], ah[mt], bh[nt]);
                    mma_bf16(acc[mt][nt], ah[mt], bl[nt]);
                    mma_bf16(acc[mt][nt], al[mt], bh[nt]);
                }
        }
        if (c < 7) asm volatile("cp.async.wait_group 0;");
        __syncthreads();
    }

    #pragma unroll
    for (int mt = 0; mt < 2; mt++) {
        int row = m0 + wm + mt * 16 + (lane >> 2);
        #pragma unroll
        for (int nt = 0; nt < 2; nt++) {
            int col = n0 + wn + nt * 8 + (lane & 3) * 2;
            if (col >= cmax) continue;
            float b0 = bias ? bias[col] : 0.f;
            float b1 = bias ? bias[col + 1] : 0.f;
            if (row < rmax)
                *reinterpret_cast<float2*>(C + (size_t)row * ldc + col) =
                    make_float2(acc[mt][nt][0] + b0, acc[mt][nt][1] + b1);
            if (row + 8 < rmax)
                *reinterpret_cast<float2*>(C + (size_t)(row + 8) * ldc + col) =
                    make_float2(acc[mt][nt][2] + b0, acc[mt][nt][3] + b1);
        }
    }
}

// ============================ fused aggregation ============================
// blocks <128: sample aggregation; blocks 128..255: proxy split-K partials (layer 1 only).
#define BM 64
#define BN 64
#define BK 16
__global__ void k_agg(const float* __restrict__ HW, const float* __restrict__ bias,
                      float* __restrict__ hout, int layer) {
    __shared__ float As[BK][BM];
    __shared__ float Bs[BK][BN];
    int tid = threadIdx.x;
    int tx = tid & 15, ty = tid >> 4;
    int la = tid * 4;
    int ar = la >> 4, ac = la & 15;
    int br = la >> 6, bc = la & 63;
    float acc[4][4] = {};

    if (blockIdx.x < 128) {
        int m0 = (blockIdx.x >> 3) * BM, n0 = (blockIdx.x & 7) * BN;
        #pragma unroll
        for (int k0 = 0; k0 < KPAD; k0 += BK) {
            float4 av = *reinterpret_cast<const float4*>(g_alphaS + (size_t)(m0 + ar) * KPAD + k0 + ac);
            As[ac + 0][ar] = av.x; As[ac + 1][ar] = av.y;
            As[ac + 2][ar] = av.z; As[ac + 3][ar] = av.w;
            float4 bv = *reinterpret_cast<const float4*>(HW + (size_t)(k0 + br) * D + n0 + bc);
            *reinterpret_cast<float4*>(&Bs[br][bc]) = bv;
            __syncthreads();
            #pragma unroll
            for (int kk = 0; kk < BK; kk++) {
                float a0 = As[kk][ty * 4 + 0], a1 = As[kk][ty * 4 + 1];
                float a2 = As[kk][ty * 4 + 2], a3 = As[kk][ty * 4 + 3];
                float b0 = Bs[kk][tx * 4 + 0], b1 = Bs[kk][tx * 4 + 1];
                float b2 = Bs[kk][tx * 4 + 2], b3 = Bs[kk][tx * 4 + 3];
                acc[0][0] += a0 * b0; acc[0][1] += a0 * b1; acc[0][2] += a0 * b2; acc[0][3] += a0 * b3;
                acc[1][0] += a1 * b0; acc[1][1] += a1 * b1; acc[1][2] += a1 * b2; acc[1][3] += a1 * b3;
                acc[2][0] += a2 * b0; acc[2][1] += a2 * b1; acc[2][2] += a2 * b2; acc[2][3] += a2 * b3;
                acc[3][0] += a3 * b0; acc[3][1] += a3 * b1; acc[3][2] += a3 * b2; acc[3][3] += a3 * b3;
            }
            __syncthreads();
        }
        int ntile = n0 >> 6;
        #pragma unroll
        for (int i = 0; i < 4; i++) {
            int r = m0 + ty * 4 + i;
            float aself = g_aselfS[r];
            int cb = n0 + tx * 4;
            float vv[4];
            #pragma unroll
            for (int j = 0; j < 4; j++) {
                float v = acc[i][j] + aself * HW[(size_t)(NP + r) * D + cb + j] + bias[cb + j];
                vv[j] = v > 0.f ? v : 0.f;
            }
            int arow = (layer == 1) ? (NP + r) : r;
            int abase = arow * D + cb;
            __nv_bfloat16 h0 = __float2bfloat16(vv[0]), h1 = __float2bfloat16(vv[1]);
            __nv_bfloat16 h2 = __float2bfloat16(vv[2]), h3 = __float2bfloat16(vv[3]);
            *reinterpret_cast<__nv_bfloat162*>(g_Ah + abase)     = __nv_bfloat162(h0, h1);
            *reinterpret_cast<__nv_bfloat162*>(g_Ah + abase + 2) = __nv_bfloat162(h2, h3);
            *reinterpret_cast<__nv_bfloat162*>(g_Al + abase) =
                __nv_bfloat162(__float2bfloat16(vv[0] - __bfloat162float(h0)),
                               __float2bfloat16(vv[1] - __bfloat162float(h1)));
            *reinterpret_cast<__nv_bfloat162*>(g_Al + abase + 2) =
                __nv_bfloat162(__float2bfloat16(vv[2] - __bfloat162float(h2)),
                               __float2bfloat16(vv[3] - __bfloat162float(h3)));
            if (layer == 2) {
                *reinterpret_cast<float4*>(hout + (size_t)r * D + cb) =
                    make_float4(vv[0], vv[1], vv[2], vv[3]);
            } else {
                float s = vv[0] * g_v[2][cb] + vv[1] * g_v[2][cb + 1]
                        + vv[2] * g_v[2][cb + 2] + vv[3] * g_v[2][cb + 3];
                float t = vv[0] * g_v[3][cb] + vv[1] * g_v[3][cb + 1]
                        + vv[2] * g_v[3][cb + 2] + vv[3] * g_v[3][cb + 3];
                #pragma unroll
                for (int o = 1; o < 16; o <<= 1) {
                    s += __shfl_xor_sync(0xffffffffu, s, o);
                    t += __shfl_xor_sync(0xffffffffu, t, o);
                }
                if (tx == 0) { g_lp[ntile][NP + r][0] = s; g_lp[ntile][NP + r][1] = t; }
            }
        }
    } else {
        int b = blockIdx.x - 128;            // (8 ntiles, 2 mtiles, 8 splits)
        int n0 = (b & 7) * BN;
        int m0 = ((b >> 3) & 1) * BM;
        int z = b >> 4;
        int kbase = z * (NS / SPLITK);
        #pragma unroll
        for (int kk0 = 0; kk0 < NS / SPLITK; kk0 += BK) {
            int k0 = kbase + kk0;
            float4 av = make_float4(0.f, 0.f, 0.f, 0.f);
            if (m0 + ar < NP)
                av = *reinterpret_cast<const float4*>(g_alphaP + (size_t)(m0 + ar) * NS + k0 + ac);
            As[ac + 0][ar] = av.x; As[ac + 1][ar] = av.y;
            As[ac + 2][ar] = av.z; As[ac + 3][ar] = av.w;
            float4 bv = *reinterpret_cast<const float4*>(HW + (size_t)(NP + k0 + br) * D + n0 + bc);
            *reinterpret_cast<float4*>(&Bs[br][bc]) = bv;
            __syncthreads();
            #pragma unroll
            for (int kk = 0; kk < BK; kk++) {
                float a0 = As[kk][ty * 4 + 0], a1 = As[kk][ty * 4 + 1];
                float a2 = As[kk][ty * 4 + 2], a3 = As[kk][ty * 4 + 3];
                float b0 = Bs[kk][tx * 4 + 0], b1 = Bs[kk][tx * 4 + 1];
                float b2 = Bs[kk][tx * 4 + 2], b3 = Bs[kk][tx * 4 + 3];
                acc[0][0] += a0 * b0; acc[0][1] += a0 * b1; acc[0][2] += a0 * b2; acc[0][3] += a0 * b3;
                acc[1][0] += a1 * b0; acc[1][1] += a1 * b1; acc[1][2] += a1 * b2; acc[1][3] += a1 * b3;
                acc[2][0] += a2 * b0; acc[2][1] += a2 * b1; acc[2][2] += a2 * b2; acc[2][3] += a2 * b3;
                acc[3][0] += a3 * b0; acc[3][1] += a3 * b1; acc[3][2] += a3 * b2; acc[3][3] += a3 * b3;
            }
            __syncthreads();
        }
        float* part = g_ppart + (size_t)z * NP * D;
        #pragma unroll
        for (int i = 0; i < 4; i++) {
            int r = m0 + ty * 4 + i;
            if (r >= NP) continue;
            #pragma unroll
            for (int j = 0; j < 4; j++)
                part[(size_t)r * D + n0 + tx * 4 + j] = acc[i][j];
        }
    }
}

// finalize layer-1 proxies: sum parts + self + bias, relu -> bf16 split + logit partials
__global__ void k_prox_fin(const float* __restrict__ HW, const float* __restrict__ bias) {
    __shared__ float sh[8][2];
    int idx = blockIdx.x * blockDim.x + threadIdx.x;
    int tid = threadIdx.x;
    int p = idx / D, c = idx - p * D;
    float v = 0.f;
    #pragma unroll
    for (int z = 0; z < SPLITK; z++) v += g_ppart[(size_t)z * NP * D + idx];
    v += g_aselfP[p] * HW[(size_t)p * D + c] + bias[c];
    v = v > 0.f ? v : 0.f;
    __nv_bfloat16 hi = __float2bfloat16(v);
    g_Ah[p * D + c] = hi;
    g_Al[p * D + c] = __float2bfloat16(v - __bfloat162float(hi));

    float s = v * g_v[2][c];
    float t = v * g_v[3][c];
    #pragma unroll
    for (int o = 16; o > 0; o >>= 1) {
        s += __shfl_xor_sync(0xffffffffu, s, o);
        t += __shfl_xor_sync(0xffffffffu, t, o);
    }
    if ((tid & 31) == 0) { sh[tid >> 5][0] = s; sh[tid >> 5][1] = t; }
    __syncthreads();
    if (tid == 0) {
        float ss = 0.f, tt = 0.f;
        #pragma unroll
        for (int i = 0; i < 8; i++) { ss += sh[i][0]; tt += sh[i][1]; }
        int half = (c >> 8) & 1;
        g_lp[half][p][0] = ss;
        g_lp[half][p][1] = tt;
    }
}

// ============================ launch ============================
extern "C" void kernel_launch(void* const* d_in, const int* in_sizes, int n_in,
                              void* d_out, int out_size) {
    const float* x    = (const float*)d_in[0];
    const float* prox = (const float*)d_in[1];
    const float* W1   = (const float*)d_in[2];
    const float* as1  = (const float*)d_in[3];
    const float* ad1  = (const float*)d_in[4];
    const float* b1   = (const float*)d_in[5];
    const float* W2   = (const float*)d_in[6];
    const float* as2  = (const float*)d_in[7];
    const float* ad2  = (const float*)d_in[8];
    const float* b2   = (const float*)d_in[9];
    const float* fcw  = (const float*)d_in[10];
    const float* fcb  = (const float*)d_in[11];
    float* out = (float*)d_out;

    float *pHW, *pLS, *pLD;
    __nv_bfloat16 *pAh, *pAl, *pW1h, *pW1l, *pW2h, *pW2l, *pFCh, *pFCl;
    cudaGetSymbolAddress((void**)&pHW, g_HW);
    cudaGetSymbolAddress((void**)&pLS, g_lsrc);
    cudaGetSymbolAddress((void**)&pLD, g_ldst);
    cudaGetSymbolAddress((void**)&pAh,  g_Ah);
    cudaGetSymbolAddress((void**)&pAl,  g_Al);
    cudaGetSymbolAddress((void**)&pW1h, g_W1h);
    cudaGetSymbolAddress((void**)&pW1l, g_W1l);
    cudaGetSymbolAddress((void**)&pW2h, g_W2h);
    cudaGetSymbolAddress((void**)&pW2l, g_W2l);
    cudaGetSymbolAddress((void**)&pFCh, g_FCh);
    cudaGetSymbolAddress((void**)&pFCl, g_FCl);

    cudaFuncSetAttribute(k_mma, cudaFuncAttributeMaxDynamicSharedMemorySize, 2 * STAGE_BYTES);

    k_prep<<<dim3(16, 16, 4), 256>>>(W1, W2, fcw, as1, ad1, as2, ad2);

    // ---- layer 1 (mma grid carries 228 alpha1 blocks in y-rows 18..46)
    k_cvt_log<<<MPAD, 128>>>(x, prox);
    k_mma<<<dim3(8, 47), 256, 2 * STAGE_BYTES>>>(pAh, pAl, pW1h, pW1l, pHW, D, NN, D, nullptr,
                                                 18, 1, pLS, pLD);
    k_agg<<<256, 256>>>(pHW, b1, nullptr, 1);
    k_prox_fin<<<NP * D / 256, 256>>>(pHW, b1);

    // ---- layer 2 (mma grid carries 128 alpha2 blocks in y-rows 18..33)
    k_mma<<<dim3(8, 34), 256, 2 * STAGE_BYTES>>>(pAh, pAl, pW2h, pW2l, pHW, D, NN, D, nullptr,
                                                 18, 2, nullptr, nullptr);
    k_agg<<<128, 256>>>(pHW, b2, out + NS * 100, 2);

    // ---- preds = h @ fc_w + fc_b (h bf16 split already in g_Ah/g_Al rows 0..1023)
    k_mma<<<dim3(2, 16), 256, 2 * STAGE_BYTES>>>(pAh, pAl, pFCh, pFCl, out, 100, NS, 100, fcb,
                                                 16, 0, nullptr, nullptr);
}

// round 8
// speedup vs baseline: 1.1255x; 1.1255x over previous
#include <cuda_runtime.h>
#include <cuda_bf16.h>
#include <cstdint>

#define NP 100      // proxies
#define NS 1024     // samples
#define NN 1124     // total nodes
#define MPAD 1152   // NN padded to 128
#define D  512
#define KPAD2 128   // NP padded for sample-agg K

// scratch (device globals; no allocation allowed)
__device__ float g_HW[MPAD * D];
__device__ float g_lsrc[NN];
__device__ float g_ldst[NN];
__device__ float g_aselfS[NS];
__device__ float g_aselfP[NP];
__device__ float g_v[4][D];             // W1@as1, W1@ad1, W2@as2, W2@ad2
__device__ float g_lp[8][NN][2];        // layer-2 logit partials [64col-tile][node][src/dst]
// bf16 split operands
__device__ __nv_bfloat16 g_Ah[MPAD * D];
__device__ __nv_bfloat16 g_Al[MPAD * D];
__device__ __nv_bfloat16 g_W1h[D * D];
__device__ __nv_bfloat16 g_W1l[D * D];
__device__ __nv_bfloat16 g_W2h[D * D];
__device__ __nv_bfloat16 g_W2l[D * D];
__device__ __nv_bfloat16 g_FCh[128 * D];
__device__ __nv_bfloat16 g_FCl[128 * D];
__device__ __nv_bfloat16 g_Hth[D * MPAD];   // H transposed [d][node]
__device__ __nv_bfloat16 g_Htl[D * MPAD];
__device__ __nv_bfloat16 g_aSh[NS * KPAD2]; // alpha (sample dst), K-major
__device__ __nv_bfloat16 g_aSl[NS * KPAD2];
__device__ __nv_bfloat16 g_aPh[128 * MPAD]; // alpha (proxy dst), K over all nodes
__device__ __nv_bfloat16 g_aPl[128 * MPAD];

__device__ __forceinline__ float lrelu(float v) { return v > 0.f ? v : 0.2f * v; }

__device__ __forceinline__ uint32_t smem_u32(const void* p) {
    uint32_t a;
    asm("{ .reg .u64 t; cvta.to.shared.u64 t, %1; cvt.u32.u64 %0, t; }" : "=r"(a) : "l"(p));
    return a;
}
__device__ __forceinline__ void bsplit(float v, __nv_bfloat16& hi, __nv_bfloat16& lo) {
    hi = __float2bfloat16(v);
    lo = __float2bfloat16(v - __bfloat162float(hi));
}

// ============================ prep ============================
__global__ void k_prep(const float* __restrict__ W1, const float* __restrict__ W2,
                       const float* __restrict__ fcw,
                       const float* __restrict__ as1, const float* __restrict__ ad1,
                       const float* __restrict__ as2, const float* __restrict__ ad2) {
    if (blockIdx.z < 2) {
        const float* W = blockIdx.z ? W2 : W1;
        __nv_bfloat16* Wh = blockIdx.z ? g_W2h : g_W1h;
        __nv_bfloat16* Wl = blockIdx.z ? g_W2l : g_W1l;
        __shared__ float t[32][33];
        int tx = threadIdx.x & 31, ty = threadIdx.x >> 5;
        int k0 = blockIdx.y * 32, n0 = blockIdx.x * 32;
        #pragma unroll
        for (int j = 0; j < 4; j++)
            t[ty + 8 * j][tx] = W[(size_t)(k0 + ty + 8 * j) * D + n0 + tx];
        __syncthreads();
        #pragma unroll
        for (int j = 0; j < 4; j++) {
            int n = n0 + ty + 8 * j, k = k0 + tx;
            __nv_bfloat16 hi, lo;
            bsplit(t[tx][ty + 8 * j], hi, lo);
            Wh[(size_t)n * D + k] = hi;
            Wl[(size_t)n * D + k] = lo;
        }
    } else if (blockIdx.z == 2) {
        int b = blockIdx.y * 16 + blockIdx.x;
        int gw = b * 8 + (threadIdx.x >> 5);
        int lane = threadIdx.x & 31;
        int vec = gw >> 9, k = gw & 511;
        const float* W = (vec < 2) ? W1 : W2;
        const float* a = (vec == 0) ? as1 : (vec == 1) ? ad1 : (vec == 2) ? as2 : ad2;
        const float* wr = W + (size_t)k * D;
        float s = 0.f;
        #pragma unroll 4
        for (int n = lane; n < D; n += 32) s += wr[n] * a[n];
        #pragma unroll
        for (int o = 16; o > 0; o >>= 1) s += __shfl_xor_sync(0xffffffffu, s, o);
        if (lane == 0) g_v[vec][k] = s;
    } else {
        if (blockIdx.x >= 4) return;
        __shared__ float t[32][33];
        int tx = threadIdx.x & 31, ty = threadIdx.x >> 5;
        int k0 = blockIdx.y * 32, n0 = blockIdx.x * 32;
        #pragma unroll
        for (int j = 0; j < 4; j++) {
            int n = n0 + tx;
            t[ty + 8 * j][tx] = (n < 100) ? fcw[(size_t)(k0 + ty + 8 * j) * 100 + n] : 0.f;
        }
        __syncthreads();
        #pragma unroll
        for (int j = 0; j < 4; j++) {
            int n = n0 + ty + 8 * j, k = k0 + tx;
            __nv_bfloat16 hi, lo;
            bsplit(t[tx][ty + 8 * j], hi, lo);
            g_FCh[(size_t)n * D + k] = hi;
            g_FCl[(size_t)n * D + k] = lo;
        }
    }
}

// ============================ layer-1 convert + logits ============================
__global__ void k_cvt_log(const float* __restrict__ x, const float* __restrict__ prox) {
    __shared__ float sh[8];
    int row = blockIdx.x, tid = threadIdx.x;
    int base = row * D + tid * 4;

    float4 v = make_float4(0.f, 0.f, 0.f, 0.f);
    if (row < NP)      v = *reinterpret_cast<const float4*>(prox + base);
    else if (row < NN) v = *reinterpret_cast<const float4*>(x + base - NP * D);

    __nv_bfloat16 h0, h1, h2, h3, l0, l1, l2, l3;
    bsplit(v.x, h0, l0); bsplit(v.y, h1, l1); bsplit(v.z, h2, l2); bsplit(v.w, h3, l3);
    *reinterpret_cast<__nv_bfloat162*>(g_Ah + base)     = __nv_bfloat162(h0, h1);
    *reinterpret_cast<__nv_bfloat162*>(g_Ah + base + 2) = __nv_bfloat162(h2, h3);
    *reinterpret_cast<__nv_bfloat162*>(g_Al + base)     = __nv_bfloat162(l0, l1);
    *reinterpret_cast<__nv_bfloat162*>(g_Al + base + 2) = __nv_bfloat162(l2, l3);

    if (row >= NN) return;

    float4 vs = *reinterpret_cast<const float4*>(&g_v[0][tid * 4]);
    float4 vd = *reinterpret_cast<const float4*>(&g_v[1][tid * 4]);
    float s = v.x * vs.x + v.y * vs.y + v.z * vs.z + v.w * vs.w;
    float t = v.x * vd.x + v.y * vd.y + v.z * vd.z + v.w * vd.w;
    #pragma unroll
    for (int o = 16; o > 0; o >>= 1) {
        s += __shfl_xor_sync(0xffffffffu, s, o);
        t += __shfl_xor_sync(0xffffffffu, t, o);
    }
    if ((tid & 31) == 0) { sh[tid >> 5] = s; sh[4 + (tid >> 5)] = t; }
    __syncthreads();
    if (tid == 0) g_lsrc[row] = sh[0] + sh[1] + sh[2] + sh[3];
    if (tid == 32) g_ldst[row] = sh[4] + sh[5] + sh[6] + sh[7];
}

// ============================ mma common ============================
#define SWB(r, b) ((r) * 128 + ((b) ^ (((r) & 7) << 4)))
#define STAGE_BYTES 32768

__device__ __forceinline__ void ldm_x4(uint32_t* f, uint32_t addr) {
    asm volatile("ldmatrix.sync.aligned.m8n8.x4.shared.b16 {%0,%1,%2,%3}, [%4];"
                 : "=r"(f[0]), "=r"(f[1]), "=r"(f[2]), "=r"(f[3]) : "r"(addr));
}
__device__ __forceinline__ void ldm_x2(uint32_t* f, uint32_t addr) {
    asm volatile("ldmatrix.sync.aligned.m8n8.x2.shared.b16 {%0,%1}, [%2];"
                 : "=r"(f[0]), "=r"(f[1]) : "r"(addr));
}
__device__ __forceinline__ void mma_bf16(float* c, const uint32_t* a, const uint32_t* b) {
    asm volatile(
        "mma.sync.aligned.m16n8k16.row.col.f32.bf16.bf16.f32 "
        "{%0,%1,%2,%3}, {%4,%5,%6,%7}, {%8,%9}, {%0,%1,%2,%3};"
        : "+f"(c[0]), "+f"(c[1]), "+f"(c[2]), "+f"(c[3])
        : "r"(a[0]), "r"(a[1]), "r"(a[2]), "r"(a[3]), "r"(b[0]), "r"(b[1]));
}
__device__ __forceinline__ void cpa16(uint32_t saddr, const void* g) {
    asm volatile("cp.async.cg.shared.global [%0], [%1], 16;" :: "r"(saddr), "l"(g));
}

// pipelined mainloop shared by both mma kernels
#define MMA_MAINLOOP(AH, AL, BH, BL, LDA, LDB, NCHUNK)                                   \
    int li = tid * 2;                                                                    \
    int lr0 = li >> 3, ls0 = li & 7;                                                     \
    int lr1 = (li + 1) >> 3, ls1 = (li + 1) & 7;                                         \
    int a_r = (lane & 7) + ((lane >> 3) & 1) * 8;                                        \
    int a_kb = (lane >> 4) * 16;                                                         \
    int b_r = lane & 7;                                                                  \
    int b_kb = ((lane >> 3) & 1) * 16;                                                   \
    float acc[2][2][4] = {};                                                             \
    auto issue = [&](int c, int st) {                                                    \
        int kc = c * 64;                                                                 \
        uint32_t stb = sb + st * STAGE_BYTES;                                            \
        cpa16(stb + SWB(lr0, ls0 * 16), (AH) + (size_t)(m0 + lr0) * (LDA) + kc + ls0 * 8); \
        cpa16(stb + SWB(lr1, ls1 * 16), (AH) + (size_t)(m0 + lr1) * (LDA) + kc + ls1 * 8); \
        cpa16(stb + 8192 + SWB(lr0, ls0 * 16), (AL) + (size_t)(m0 + lr0) * (LDA) + kc + ls0 * 8); \
        cpa16(stb + 8192 + SWB(lr1, ls1 * 16), (AL) + (size_t)(m0 + lr1) * (LDA) + kc + ls1 * 8); \
        cpa16(stb + 16384 + SWB(lr0, ls0 * 16), (BH) + (size_t)(n0 + lr0) * (LDB) + kc + ls0 * 8); \
        cpa16(stb + 16384 + SWB(lr1, ls1 * 16), (BH) + (size_t)(n0 + lr1) * (LDB) + kc + ls1 * 8); \
        cpa16(stb + 24576 + SWB(lr0, ls0 * 16), (BL) + (size_t)(n0 + lr0) * (LDB) + kc + ls0 * 8); \
        cpa16(stb + 24576 + SWB(lr1, ls1 * 16), (BL) + (size_t)(n0 + lr1) * (LDB) + kc + ls1 * 8); \
        asm volatile("cp.async.commit_group;");                                          \
    };                                                                                   \
    issue(0, 0);                                                                         \
    asm volatile("cp.async.wait_group 0;");                                              \
    __syncthreads();                                                                     \
    for (int c = 0; c < (NCHUNK); c++) {                                                 \
        int st = c & 1;                                                                  \
        if (c + 1 < (NCHUNK)) issue(c + 1, st ^ 1);                                      \
        uint32_t stb = sb + st * STAGE_BYTES;                                            \
        _Pragma("unroll")                                                                \
        for (int ks = 0; ks < 4; ks++) {                                                 \
            int kb = ks * 32;                                                            \
            uint32_t ah[2][4], al[2][4], bh[2][2], bl[2][2];                             \
            _Pragma("unroll")                                                            \
            for (int mt = 0; mt < 2; mt++) {                                             \
                int r = wm + mt * 16 + a_r;                                              \
                ldm_x4(ah[mt], stb + 0    + SWB(r, kb + a_kb));                          \
                ldm_x4(al[mt], stb + 8192 + SWB(r, kb + a_kb));                          \
            }                                                                            \
            _Pragma("unroll")                                                            \
            for (int nt = 0; nt < 2; nt++) {                                             \
                int r = wn + nt * 8 + b_r;                                               \
                ldm_x2(bh[nt], stb + 16384 + SWB(r, kb + b_kb));                         \
                ldm_x2(bl[nt], stb + 24576 + SWB(r, kb + b_kb));                         \
            }                                                                            \
            _Pragma("unroll")                                                            \
            for (int mt = 0; mt < 2; mt++)                                               \
                _Pragma("unroll")                                                        \
                for (int nt = 0; nt < 2; nt++) {                                         \
                    mma_bf16(acc[mt][nt], ah[mt], bh[nt]);                               \
                    mma_bf16(acc[mt][nt], ah[mt], bl[nt]);                               \
                    mma_bf16(acc[mt][nt], al[mt], bh[nt]);                               \
                }                                                                        \
        }                                                                                \
        if (c + 1 < (NCHUNK)) asm volatile("cp.async.wait_group 0;");                    \
        __syncthreads();                                                                 \
    }

// ============================ layer GEMM / FC GEMM ============================
// mode 0: FC -> C fp32 (ldc=100, guards) + bias. mode 1: H = A@W -> g_HW fp32 + Ht bf16 split.
__global__ void __launch_bounds__(256, 1) k_mma(
    const __nv_bfloat16* __restrict__ Ah, const __nv_bfloat16* __restrict__ Al,
    const __nv_bfloat16* __restrict__ Bh, const __nv_bfloat16* __restrict__ Bl,
    float* __restrict__ C, const float* __restrict__ bias, int mode) {
    extern __shared__ __align__(16) char sm[];
    int tid = threadIdx.x, wid = tid >> 5, lane = tid & 31;
    int n0 = blockIdx.x * 64, m0 = blockIdx.y * 64;
    int wm = (wid >> 2) * 32, wn = (wid & 3) * 16;
    uint32_t sb = smem_u32(sm);

    MMA_MAINLOOP(Ah, Al, Bh, Bl, D, D, 8)

    if (mode == 0) {
        #pragma unroll
        for (int mt = 0; mt < 2; mt++) {
            int row = m0 + wm + mt * 16 + (lane >> 2);
            #pragma unroll
            for (int nt = 0; nt < 2; nt++) {
                int col = n0 + wn + nt * 8 + (lane & 3) * 2;
                if (col >= 100) continue;
                float b0 = bias[col], b1 = bias[col + 1];
                *reinterpret_cast<float2*>(C + (size_t)row * 100 + col) =
                    make_float2(acc[mt][nt][0] + b0, acc[mt][nt][1] + b1);
                *reinterpret_cast<float2*>(C + (size_t)(row + 8) * 100 + col) =
                    make_float2(acc[mt][nt][2] + b0, acc[mt][nt][3] + b1);
            }
        }
    } else {
        // fp32 HW store (full MPAD rows; pad rows are zero since A rows are zero)
        #pragma unroll
        for (int mt = 0; mt < 2; mt++) {
            int row = m0 + wm + mt * 16 + (lane >> 2);
            #pragma unroll
            for (int nt = 0; nt < 2; nt++) {
                int col = n0 + wn + nt * 8 + (lane & 3) * 2;
                *reinterpret_cast<float2*>(g_HW + (size_t)row * D + col) =
                    make_float2(acc[mt][nt][0], acc[mt][nt][1]);
                *reinterpret_cast<float2*>(g_HW + (size_t)(row + 8) * D + col) =
                    make_float2(acc[mt][nt][2], acc[mt][nt][3]);
            }
        }
        // transpose via smem, write Ht bf16 split
        float* ts = reinterpret_cast<float*>(sm);   // [64][65]
        #pragma unroll
        for (int mt = 0; mt < 2; mt++)
            #pragma unroll
            for (int nt = 0; nt < 2; nt++)
                #pragma unroll
                for (int j = 0; j < 4; j++) {
                    int rl = wm + mt * 16 + (lane >> 2) + (j >> 1) * 8;
                    int cl = wn + nt * 8 + (lane & 3) * 2 + (j & 1);
                    ts[rl * 65 + cl] = acc[mt][nt][j];
                }
        __syncthreads();
        #pragma unroll
        for (int it = 0; it < 16; it++) {
            int lin = it * 256 + tid;
            int n = lin >> 6, m = lin & 63;
            __nv_bfloat16 hi, lo;
            bsplit(ts[m * 65 + n], hi, lo);
            g_Hth[(size_t)(n0 + n) * MPAD + m0 + m] = hi;
            g_Htl[(size_t)(n0 + n) * MPAD + m0 + m] = lo;
        }
    }
}

// ============================ alpha layer 1 ============================
// blocks 0..127: samples (8 warps, 1 sample each). 128..227: proxies. 228..255: zero pad rows.
__global__ void k_alpha(const float* __restrict__ lsrc, const float* __restrict__ ldst) {
    int tid = threadIdx.x;
    int b = blockIdx.x;
    if (b < 128) {
        int warp = b * 8 + (tid >> 5);
        int lane = tid & 31;
        int node = NP + warp;
        float ld = ldst[node];
        float w[4], sum = 0.f;
        #pragma unroll
        for (int i = 0; i < 4; i++) {
            int p = lane + 32 * i;
            w[i] = (p < NP) ? __expf(lrelu(lsrc[p] + ld)) : 0.f;
            sum += w[i];
        }
        float wself = __expf(lrelu(lsrc[node] + ld));
        #pragma unroll
        for (int o = 16; o > 0; o >>= 1) sum += __shfl_xor_sync(0xffffffffu, sum, o);
        float inv = 1.f / (sum + wself);
        #pragma unroll
        for (int i = 0; i < 4; i++) {
            int p = lane + 32 * i;
            __nv_bfloat16 hi, lo;
            bsplit(w[i] * inv, hi, lo);
            g_aSh[(size_t)warp * KPAD2 + p] = hi;
            g_aSl[(size_t)warp * KPAD2 + p] = lo;
        }
        if (lane == 0) g_aselfS[warp] = wself * inv;
    } else if (b < 228) {
        __shared__ float sh[8];
        __shared__ float s_inv;
        int p = b - 128;
        float ld = ldst[p];
        float w[4], sum = 0.f;
        #pragma unroll
        for (int i = 0; i < 4; i++) {
            w[i] = __expf(lrelu(lsrc[NP + tid + i * 256] + ld));
            sum += w[i];
        }
        float wself = __expf(lrelu(lsrc[p] + ld));
        #pragma unroll
        for (int o = 16; o > 0; o >>= 1) sum += __shfl_xor_sync(0xffffffffu, sum, o);
        if ((tid & 31) == 0) sh[tid >> 5] = sum;
        __syncthreads();
        if (tid == 0) {
            float ss = 0.f;
            #pragma unroll
            for (int i = 0; i < 8; i++) ss += sh[i];
            s_inv = 1.f / (ss + wself);
        }
        __syncthreads();
        float inv = s_inv;
        #pragma unroll
        for (int i = 0; i < 4; i++) {
            int col = NP + tid + i * 256;
            __nv_bfloat16 hi, lo;
            bsplit(w[i] * inv, hi, lo);
            g_aPh[(size_t)p * MPAD + col] = hi;
            g_aPl[(size_t)p * MPAD + col] = lo;
        }
        __nv_bfloat16 z = __float2bfloat16(0.f);
        if (tid < NP) { g_aPh[(size_t)p * MPAD + tid] = z; g_aPl[(size_t)p * MPAD + tid] = z; }
        if (tid < MPAD - NN) {
            g_aPh[(size_t)p * MPAD + NN + tid] = z;
            g_aPl[(size_t)p * MPAD + NN + tid] = z;
        }
        if (tid == 0) g_aselfP[p] = wself * inv;
    } else {
        // zero alphaP pad rows 100..127
        int p = 100 + (b - 228);
        uint32_t* h = reinterpret_cast<uint32_t*>(g_aPh + (size_t)p * MPAD);
        uint32_t* l = reinterpret_cast<uint32_t*>(g_aPl + (size_t)p * MPAD);
        for (int i = tid; i < MPAD / 2; i += 256) { h[i] = 0u; l[i] = 0u; }
    }
}

// ============================ alpha layer 2 (samples only, from g_lp) ============================
__global__ void k_alpha2() {
    int warp = blockIdx.x * 8 + (threadIdx.x >> 5);
    int lane = threadIdx.x & 31;
    int node = NP + warp;
    float lsn = 0.f, ldn = 0.f;
    #pragma unroll
    for (int ti = 0; ti < 8; ti++) {
        lsn += g_lp[ti][node][0];
        ldn += g_lp[ti][node][1];
    }
    float w[4], sum = 0.f;
    #pragma unroll
    for (int i = 0; i < 4; i++) {
        int p = lane + 32 * i;
        if (p < NP) {
            float lsp = 0.f;
            #pragma unroll
            for (int ti = 0; ti < 8; ti++) lsp += g_lp[ti][p][0];
            w[i] = __expf(lrelu(lsp + ldn));
        } else w[i] = 0.f;
        sum += w[i];
    }
    float wself = __expf(lrelu(lsn + ldn));
    #pragma unroll
    for (int o = 16; o > 0; o >>= 1) sum += __shfl_xor_sync(0xffffffffu, sum, o);
    float inv = 1.f / (sum + wself);
    #pragma unroll
    for (int i = 0; i < 4; i++) {
        int p = lane + 32 * i;
        __nv_bfloat16 hi, lo;
        bsplit(w[i] * inv, hi, lo);
        g_aSh[(size_t)warp * KPAD2 + p] = hi;
        g_aSl[(size_t)warp * KPAD2 + p] = lo;
    }
    if (lane == 0) g_aselfS[warp] = wself * inv;
}

// ============================ aggregation GEMM (tensor cores) ============================
// layer 1, grid 144: blocks 0..127 sample tiles; 128..143 proxy tiles (K=1152).
// layer 2, grid 128: sample tiles only.
__global__ void __launch_bounds__(256, 1) k_aggm(const float* __restrict__ bias,
                                                 float* __restrict__ hout, int layer) {
    extern __shared__ __align__(16) char sm[];
    int tid = threadIdx.x, wid = tid >> 5, lane = tid & 31;
    int wm = (wid >> 2) * 32, wn = (wid & 3) * 16;
    uint32_t sb = smem_u32(sm);
    int b = blockIdx.x;
    bool isprox = (b >= 128);

    int m0, n0;
    if (!isprox) { m0 = (b >> 3) * 64; n0 = (b & 7) * 64; }
    else { int bb = b - 128; m0 = (bb >> 3) * 64; n0 = (bb & 7) * 64; }

    if (!isprox) {
        MMA_MAINLOOP(g_aSh, g_aSl, g_Hth, g_Htl, KPAD2, MPAD, 2)
        // epilogue: v = acc + aself*HW[NP+r] + bias, relu
        #pragma unroll
        for (int mt = 0; mt < 2; mt++)
            #pragma unroll
            for (int nt = 0; nt < 2; nt++)
                #pragma unroll
                for (int j = 0; j < 4; j++) {
                    int r = m0 + wm + mt * 16 + (lane >> 2) + (j >> 1) * 8;
                    int col = n0 + wn + nt * 8 + (lane & 3) * 2 + (j & 1);
                    float v = acc[mt][nt][j] + g_aselfS[r] * g_HW[(size_t)(NP + r) * D + col]
                            + bias[col];
                    acc[mt][nt][j] = v > 0.f ? v : 0.f;
                }
        #pragma unroll
        for (int mt = 0; mt < 2; mt++)
            #pragma unroll
            for (int half = 0; half < 2; half++) {
                int r = m0 + wm + mt * 16 + (lane >> 2) + half * 8;
                int arow = (layer == 1) ? (NP + r) : r;
                #pragma unroll
                for (int nt = 0; nt < 2; nt++) {
                    int col = n0 + wn + nt * 8 + (lane & 3) * 2;
                    float v0 = acc[mt][nt][half * 2], v1 = acc[mt][nt][half * 2 + 1];
                    __nv_bfloat16 h0, h1, l0, l1;
                    bsplit(v0, h0, l0); bsplit(v1, h1, l1);
                    *reinterpret_cast<__nv_bfloat162*>(g_Ah + (size_t)arow * D + col) =
                        __nv_bfloat162(h0, h1);
                    *reinterpret_cast<__nv_bfloat162*>(g_Al + (size_t)arow * D + col) =
                        __nv_bfloat162(l0, l1);
                    if (layer == 2)
                        *reinterpret_cast<float2*>(hout + (size_t)r * D + col) =
                            make_float2(v0, v1);
                }
            }
        if (layer == 1) {
            // logit partials: per-row 64-col sums via shfl + smem
            float* lpb = reinterpret_cast<float*>(sm);   // [64][4][2]
            __syncthreads();
            #pragma unroll
            for (int mt = 0; mt < 2; mt++)
                #pragma unroll
                for (int half = 0; half < 2; half++) {
                    int rl = wm + mt * 16 + (lane >> 2) + half * 8;
                    float s = 0.f, t = 0.f;
                    #pragma unroll
                    for (int nt = 0; nt < 2; nt++) {
                        int col = n0 + wn + nt * 8 + (lane & 3) * 2;
                        float v0 = acc[mt][nt][half * 2], v1 = acc[mt][nt][half * 2 + 1];
                        s += v0 * g_v[2][col] + v1 * g_v[2][col + 1];
                        t += v0 * g_v[3][col] + v1 * g_v[3][col + 1];
                    }
                    s += __shfl_xor_sync(0xffffffffu, s, 1);
                    s += __shfl_xor_sync(0xffffffffu, s, 2);
                    t += __shfl_xor_sync(0xffffffffu, t, 1);
                    t += __shfl_xor_sync(0xffffffffu, t, 2);
                    if ((lane & 3) == 0) {
                        lpb[(rl * 4 + (wid & 3)) * 2 + 0] = s;
                        lpb[(rl * 4 + (wid & 3)) * 2 + 1] = t;
                    }
                }
            __syncthreads();
            if (tid < 128) {
                int rl = tid >> 1, comp = tid & 1;
                float s = lpb[(rl * 4 + 0) * 2 + comp] + lpb[(rl * 4 + 1) * 2 + comp]
                        + lpb[(rl * 4 + 2) * 2 + comp] + lpb[(rl * 4 + 3) * 2 + comp];
                g_lp[n0 >> 6][NP + m0 + rl][comp] = s;
            }
        }
    } else {
        MMA_MAINLOOP(g_aPh, g_aPl, g_Hth, g_Htl, MPAD, MPAD, 18)
        #pragma unroll
        for (int mt = 0; mt < 2; mt++)
            #pragma unroll
            for (int nt = 0; nt < 2; nt++)
                #pragma unroll
                for (int j = 0; j < 4; j++) {
                    int p = m0 + wm + mt * 16 + (lane >> 2) + (j >> 1) * 8;
                    int col = n0 + wn + nt * 8 + (lane & 3) * 2 + (j & 1);
                    if (p < NP) {
                        float v = acc[mt][nt][j] + g_aselfP[p] * g_HW[(size_t)p * D + col]
                                + bias[col];
                        acc[mt][nt][j] = v > 0.f ? v : 0.f;
                    } else acc[mt][nt][j] = 0.f;
                }
        #pragma unroll
        for (int mt = 0; mt < 2; mt++)
            #pragma unroll
            for (int half = 0; half < 2; half++) {
                int p = m0 + wm + mt * 16 + (lane >> 2) + half * 8;
                if (p >= NP) continue;
                #pragma unroll
                for (int nt = 0; nt < 2; nt++) {
                    int col = n0 + wn + nt * 8 + (lane & 3) * 2;
                    float v0 = acc[mt][nt][half * 2], v1 = acc[mt][nt][half * 2 + 1];
                    __nv_bfloat16 h0, h1, l0, l1;
                    bsplit(v0, h0, l0); bsplit(v1, h1, l1);
                    *reinterpret_cast<__nv_bfloat162*>(g_Ah + (size_t)p * D + col) =
                        __nv_bfloat162(h0, h1);
                    *reinterpret_cast<__nv_bfloat162*>(g_Al + (size_t)p * D + col) =
                        __nv_bfloat162(l0, l1);
                }
            }
        // logit partials
        float* lpb = reinterpret_cast<float*>(sm);
        __syncthreads();
        #pragma unroll
        for (int mt = 0; mt < 2; mt++)
            #pragma unroll
            for (int half = 0; half < 2; half++) {
                int rl = wm + mt * 16 + (lane >> 2) + half * 8;
                float s = 0.f, t = 0.f;
                #pragma unroll
                for (int nt = 0; nt < 2; nt++) {
                    int col = n0 + wn + nt * 8 + (lane & 3) * 2;
                    float v0 = acc[mt][nt][half * 2], v1 = acc[mt][nt][half * 2 + 1];
                    s += v0 * g_v[2][col] + v1 * g_v[2][col + 1];
                    t += v0 * g_v[3][col] + v1 * g_v[3][col + 1];
                }
                s += __shfl_xor_sync(0xffffffffu, s, 1);
                s += __shfl_xor_sync(0xffffffffu, s, 2);
                t += __shfl_xor_sync(0xffffffffu, t, 1);
                t += __shfl_xor_sync(0xffffffffu, t, 2);
                if ((lane & 3) == 0) {
                    lpb[(rl * 4 + (wid & 3)) * 2 + 0] = s;
                    lpb[(rl * 4 + (wid & 3)) * 2 + 1] = t;
                }
            }
        __syncthreads();
        if (tid < 128) {
            int rl = tid >> 1, comp = tid & 1;
            int p = m0 + rl;
            if (p < NP) {
                float s = lpb[(rl * 4 + 0) * 2 + comp] + lpb[(rl * 4 + 1) * 2 + comp]
                        + lpb[(rl * 4 + 2) * 2 + comp] + lpb[(rl * 4 + 3) * 2 + comp];
                g_lp[n0 >> 6][p][comp] = s;
            }
        }
    }
}

// ============================ launch ============================
extern "C" void kernel_launch(void* const* d_in, const int* in_sizes, int n_in,
                              void* d_out, int out_size) {
    const float* x    = (const float*)d_in[0];
    const float* prox = (const float*)d_in[1];
    const float* W1   = (const float*)d_in[2];
    const float* as1  = (const float*)d_in[3];
    const float* ad1  = (const float*)d_in[4];
    const float* b1   = (const float*)d_in[5];
    const float* W2   = (const float*)d_in[6];
    const float* as2  = (const float*)d_in[7];
    const float* ad2  = (const float*)d_in[8];
    const float* b2   = (const float*)d_in[9];
    const float* fcw  = (const float*)d_in[10];
    const float* fcb  = (const float*)d_in[11];
    float* out = (float*)d_out;

    float *pLS, *pLD;
    __nv_bfloat16 *pAh, *pAl, *pW1h, *pW1l, *pW2h, *pW2l, *pFCh, *pFCl;
    cudaGetSymbolAddress((void**)&pLS, g_lsrc);
    cudaGetSymbolAddress((void**)&pLD, g_ldst);
    cudaGetSymbolAddress((void**)&pAh,  g_Ah);
    cudaGetSymbolAddress((void**)&pAl,  g_Al);
    cudaGetSymbolAddress((void**)&pW1h, g_W1h);
    cudaGetSymbolAddress((void**)&pW1l, g_W1l);
    cudaGetSymbolAddress((void**)&pW2h, g_W2h);
    cudaGetSymbolAddress((void**)&pW2l, g_W2l);
    cudaGetSymbolAddress((void**)&pFCh, g_FCh);
    cudaGetSymbolAddress((void**)&pFCl, g_FCl);

    cudaFuncSetAttribute(k_mma,  cudaFuncAttributeMaxDynamicSharedMemorySize, 2 * STAGE_BYTES);
    cudaFuncSetAttribute(k_aggm, cudaFuncAttributeMaxDynamicSharedMemorySize, 2 * STAGE_BYTES);

    k_prep<<<dim3(16, 16, 4), 256>>>(W1, W2, fcw, as1, ad1, as2, ad2);

    // ---- layer 1
    k_cvt_log<<<MPAD, 128>>>(x, prox);
    k_mma<<<dim3(8, 18), 256, 2 * STAGE_BYTES>>>(pAh, pAl, pW1h, pW1l, nullptr, nullptr, 1);
    k_alpha<<<256, 256>>>(pLS, pLD);
    k_aggm<<<144, 256, 2 * STAGE_BYTES>>>(b1, nullptr, 1);

    // ---- layer 2 (proxy aggregation unused downstream)
    k_mma<<<dim3(8, 18), 256, 2 * STAGE_BYTES>>>(pAh, pAl, pW2h, pW2l, nullptr, nullptr, 1);
    k_alpha2<<<128, 256>>>();
    k_aggm<<<128, 256, 2 * STAGE_BYTES>>>(b2, out + NS * 100, 2);

    // ---- preds = h @ fc_w + fc_b
    k_mma<<<dim3(2, 16), 256, 2 * STAGE_BYTES>>>(pAh, pAl, pFCh, pFCl, out, fcb, 0);
}

// round 9
// speedup vs baseline: 1.1590x; 1.0298x over previous
#include <cuda_runtime.h>
#include <cuda_bf16.h>
#include <cstdint>

#define NP 100      // proxies
#define NS 1024     // samples
#define NN 1124     // total nodes
#define MPAD 1152   // NN padded to 128
#define D  512
#define KPAD2 128   // NP padded for sample-agg K

// scratch (device globals; no allocation allowed)
__device__ float g_HW[MPAD * D];
__device__ float g_aselfS[NS];
__device__ float g_lp[8][NN][2];        // logit partials [64col-tile][node][src/dst]
// bf16 split operands
__device__ __nv_bfloat16 g_Ah[MPAD * D];
__device__ __nv_bfloat16 g_Al[MPAD * D];
__device__ __nv_bfloat16 g_W1h[D * D];
__device__ __nv_bfloat16 g_W1l[D * D];
__device__ __nv_bfloat16 g_W2h[D * D];
__device__ __nv_bfloat16 g_W2l[D * D];
__device__ __nv_bfloat16 g_FCh[128 * D];
__device__ __nv_bfloat16 g_FCl[128 * D];
__device__ __nv_bfloat16 g_Hth[D * MPAD];   // H transposed [d][node]
__device__ __nv_bfloat16 g_Htl[D * MPAD];
__device__ __nv_bfloat16 g_aSh[NS * KPAD2]; // alpha (sample dst), K-major
__device__ __nv_bfloat16 g_aSl[NS * KPAD2];
__device__ __nv_bfloat16 g_aPh[128 * MPAD]; // alpha (proxy dst), K over all nodes, self on diag
__device__ __nv_bfloat16 g_aPl[128 * MPAD];

__device__ __forceinline__ float lrelu(float v) { return v > 0.f ? v : 0.2f * v; }

__device__ __forceinline__ uint32_t smem_u32(const void* p) {
    uint32_t a;
    asm("{ .reg .u64 t; cvta.to.shared.u64 t, %1; cvt.u32.u64 %0, t; }" : "=r"(a) : "l"(p));
    return a;
}
__device__ __forceinline__ void bsplit(float v, __nv_bfloat16& hi, __nv_bfloat16& lo) {
    hi = __float2bfloat16(v);
    lo = __float2bfloat16(v - __bfloat162float(hi));
}

// ============================ setup: W splits + input convert ============================
// linear grid 1152 blocks, 256 thr:
//   0..255   W1 transpose/split   256..511 W2   512..575 fcw   576..1151 input convert (2 rows/blk)
__global__ void k_setup(const float* __restrict__ W1, const float* __restrict__ W2,
                        const float* __restrict__ fcw,
                        const float* __restrict__ x, const float* __restrict__ prox) {
    int b = blockIdx.x;
    if (b < 512) {
        const float* W = (b >= 256) ? W2 : W1;
        __nv_bfloat16* Wh = (b >= 256) ? g_W2h : g_W1h;
        __nv_bfloat16* Wl = (b >= 256) ? g_W2l : g_W1l;
        int bb = b & 255;
        __shared__ float t[32][33];
        int tx = threadIdx.x & 31, ty = threadIdx.x >> 5;
        int n0 = (bb & 15) * 32, k0 = (bb >> 4) * 32;
        #pragma unroll
        for (int j = 0; j < 4; j++)
            t[ty + 8 * j][tx] = W[(size_t)(k0 + ty + 8 * j) * D + n0 + tx];
        __syncthreads();
        #pragma unroll
        for (int j = 0; j < 4; j++) {
            int n = n0 + ty + 8 * j, k = k0 + tx;
            __nv_bfloat16 hi, lo;
            bsplit(t[tx][ty + 8 * j], hi, lo);
            Wh[(size_t)n * D + k] = hi;
            Wl[(size_t)n * D + k] = lo;
        }
    } else if (b < 576) {
        int bb = b - 512;
        __shared__ float t[32][33];
        int tx = threadIdx.x & 31, ty = threadIdx.x >> 5;
        int n0 = (bb & 3) * 32, k0 = (bb >> 2) * 32;
        #pragma unroll
        for (int j = 0; j < 4; j++) {
            int n = n0 + tx;
            t[ty + 8 * j][tx] = (n < 100) ? fcw[(size_t)(k0 + ty + 8 * j) * 100 + n] : 0.f;
        }
        __syncthreads();
        #pragma unroll
        for (int j = 0; j < 4; j++) {
            int n = n0 + ty + 8 * j, k = k0 + tx;
            __nv_bfloat16 hi, lo;
            bsplit(t[tx][ty + 8 * j], hi, lo);
            g_FCh[(size_t)n * D + k] = hi;
            g_FCl[(size_t)n * D + k] = lo;
        }
    } else {
        int row = (b - 576) * 2 + (threadIdx.x >> 7);
        int c4 = (threadIdx.x & 127) * 4;
        int base = row * D + c4;
        float4 v = make_float4(0.f, 0.f, 0.f, 0.f);
        if (row < NP)      v = *reinterpret_cast<const float4*>(prox + base);
        else if (row < NN) v = *reinterpret_cast<const float4*>(x + base - NP * D);
        __nv_bfloat16 h0, h1, h2, h3, l0, l1, l2, l3;
        bsplit(v.x, h0, l0); bsplit(v.y, h1, l1); bsplit(v.z, h2, l2); bsplit(v.w, h3, l3);
        *reinterpret_cast<__nv_bfloat162*>(g_Ah + base)     = __nv_bfloat162(h0, h1);
        *reinterpret_cast<__nv_bfloat162*>(g_Ah + base + 2) = __nv_bfloat162(h2, h3);
        *reinterpret_cast<__nv_bfloat162*>(g_Al + base)     = __nv_bfloat162(l0, l1);
        *reinterpret_cast<__nv_bfloat162*>(g_Al + base + 2) = __nv_bfloat162(l2, l3);
    }
}

// ============================ mma common ============================
#define SWB(r, b) ((r) * 128 + ((b) ^ (((r) & 7) << 4)))
#define STAGE_BYTES 32768

__device__ __forceinline__ void ldm_x4(uint32_t* f, uint32_t addr) {
    asm volatile("ldmatrix.sync.aligned.m8n8.x4.shared.b16 {%0,%1,%2,%3}, [%4];"
                 : "=r"(f[0]), "=r"(f[1]), "=r"(f[2]), "=r"(f[3]) : "r"(addr));
}
__device__ __forceinline__ void ldm_x2(uint32_t* f, uint32_t addr) {
    asm volatile("ldmatrix.sync.aligned.m8n8.x2.shared.b16 {%0,%1}, [%2];"
                 : "=r"(f[0]), "=r"(f[1]) : "r"(addr));
}
__device__ __forceinline__ void mma_bf16(float* c, const uint32_t* a, const uint32_t* b) {
    asm volatile(
        "mma.sync.aligned.m16n8k16.row.col.f32.bf16.bf16.f32 "
        "{%0,%1,%2,%3}, {%4,%5,%6,%7}, {%8,%9}, {%0,%1,%2,%3};"
        : "+f"(c[0]), "+f"(c[1]), "+f"(c[2]), "+f"(c[3])
        : "r"(a[0]), "r"(a[1]), "r"(a[2]), "r"(a[3]), "r"(b[0]), "r"(b[1]));
}
__device__ __forceinline__ void cpa16(uint32_t saddr, const void* g) {
    asm volatile("cp.async.cg.shared.global [%0], [%1], 16;" :: "r"(saddr), "l"(g));
}

#define MMA_MAINLOOP(AH, AL, BH, BL, LDA, LDB, NCHUNK)                                   \
    int li = tid * 2;                                                                    \
    int lr0 = li >> 3, ls0 = li & 7;                                                     \
    int lr1 = (li + 1) >> 3, ls1 = (li + 1) & 7;                                         \
    int a_r = (lane & 7) + ((lane >> 3) & 1) * 8;                                        \
    int a_kb = (lane >> 4) * 16;                                                         \
    int b_r = lane & 7;                                                                  \
    int b_kb = ((lane >> 3) & 1) * 16;                                                   \
    float acc[2][2][4] = {};                                                             \
    auto issue = [&](int c, int st) {                                                    \
        int kc = c * 64;                                                                 \
        uint32_t stb = sb + st * STAGE_BYTES;                                            \
        cpa16(stb + SWB(lr0, ls0 * 16), (AH) + (size_t)(m0 + lr0) * (LDA) + kc + ls0 * 8); \
        cpa16(stb + SWB(lr1, ls1 * 16), (AH) + (size_t)(m0 + lr1) * (LDA) + kc + ls1 * 8); \
        cpa16(stb + 8192 + SWB(lr0, ls0 * 16), (AL) + (size_t)(m0 + lr0) * (LDA) + kc + ls0 * 8); \
        cpa16(stb + 8192 + SWB(lr1, ls1 * 16), (AL) + (size_t)(m0 + lr1) * (LDA) + kc + ls1 * 8); \
        cpa16(stb + 16384 + SWB(lr0, ls0 * 16), (BH) + (size_t)(n0 + lr0) * (LDB) + kc + ls0 * 8); \
        cpa16(stb + 16384 + SWB(lr1, ls1 * 16), (BH) + (size_t)(n0 + lr1) * (LDB) + kc + ls1 * 8); \
        cpa16(stb + 24576 + SWB(lr0, ls0 * 16), (BL) + (size_t)(n0 + lr0) * (LDB) + kc + ls0 * 8); \
        cpa16(stb + 24576 + SWB(lr1, ls1 * 16), (BL) + (size_t)(n0 + lr1) * (LDB) + kc + ls1 * 8); \
        asm volatile("cp.async.commit_group;");                                          \
    };                                                                                   \
    issue(0, 0);                                                                         \
    asm volatile("cp.async.wait_group 0;");                                              \
    __syncthreads();                                                                     \
    for (int c = 0; c < (NCHUNK); c++) {                                                 \
        int st = c & 1;                                                                  \
        if (c + 1 < (NCHUNK)) issue(c + 1, st ^ 1);                                      \
        uint32_t stb = sb + st * STAGE_BYTES;                                            \
        _Pragma("unroll")                                                                \
        for (int ks = 0; ks < 4; ks++) {                                                 \
            int kb = ks * 32;                                                            \
            uint32_t ah[2][4], al[2][4], bh[2][2], bl[2][2];                             \
            _Pragma("unroll")                                                            \
            for (int mt = 0; mt < 2; mt++) {                                             \
                int r = wm + mt * 16 + a_r;                                              \
                ldm_x4(ah[mt], stb + 0    + SWB(r, kb + a_kb));                          \
                ldm_x4(al[mt], stb + 8192 + SWB(r, kb + a_kb));                          \
            }                                                                            \
            _Pragma("unroll")                                                            \
            for (int nt = 0; nt < 2; nt++) {                                             \
                int r = wn + nt * 8 + b_r;                                               \
                ldm_x2(bh[nt], stb + 16384 + SWB(r, kb + b_kb));                         \
                ldm_x2(bl[nt], stb + 24576 + SWB(r, kb + b_kb));                         \
            }                                                                            \
            _Pragma("unroll")                                                            \
            for (int mt = 0; mt < 2; mt++)                                               \
                _Pragma("unroll")                                                        \
                for (int nt = 0; nt < 2; nt++) {                                         \
                    mma_bf16(acc[mt][nt], ah[mt], bh[nt]);                               \
                    mma_bf16(acc[mt][nt], ah[mt], bl[nt]);                               \
                    mma_bf16(acc[mt][nt], al[mt], bh[nt]);                               \
                }                                                                        \
        }                                                                                \
        if (c + 1 < (NCHUNK)) asm volatile("cp.async.wait_group 0;");                    \
        __syncthreads();                                                                 \
    }

// ============================ layer GEMM / FC GEMM ============================
// mode 0: FC -> C fp32 (ldc=100, col guard) + bias.
// mode 1: H = A@W -> g_HW fp32 + g_lp logit partials (H·a_src, H·a_dst) + Ht bf16 split.
__global__ void __launch_bounds__(256, 1) k_mma(
    const __nv_bfloat16* __restrict__ Ah, const __nv_bfloat16* __restrict__ Al,
    const __nv_bfloat16* __restrict__ Bh, const __nv_bfloat16* __restrict__ Bl,
    float* __restrict__ C, const float* __restrict__ bias, int mode,
    const float* __restrict__ asrc, const float* __restrict__ adst) {
    extern __shared__ __align__(16) char sm[];
    int tid = threadIdx.x, wid = tid >> 5, lane = tid & 31;
    int n0 = blockIdx.x * 64, m0 = blockIdx.y * 64;
    int wm = (wid >> 2) * 32, wn = (wid & 3) * 16;
    uint32_t sb = smem_u32(sm);

    MMA_MAINLOOP(Ah, Al, Bh, Bl, D, D, 8)

    if (mode == 0) {
        #pragma unroll
        for (int mt = 0; mt < 2; mt++) {
            int row = m0 + wm + mt * 16 + (lane >> 2);
            #pragma unroll
            for (int nt = 0; nt < 2; nt++) {
                int col = n0 + wn + nt * 8 + (lane & 3) * 2;
                if (col >= 100) continue;
                float b0 = bias[col], b1 = bias[col + 1];
                *reinterpret_cast<float2*>(C + (size_t)row * 100 + col) =
                    make_float2(acc[mt][nt][0] + b0, acc[mt][nt][1] + b1);
                *reinterpret_cast<float2*>(C + (size_t)(row + 8) * 100 + col) =
                    make_float2(acc[mt][nt][2] + b0, acc[mt][nt][3] + b1);
            }
        }
        return;
    }

    // fp32 HW store
    #pragma unroll
    for (int mt = 0; mt < 2; mt++) {
        int row = m0 + wm + mt * 16 + (lane >> 2);
        #pragma unroll
        for (int nt = 0; nt < 2; nt++) {
            int col = n0 + wn + nt * 8 + (lane & 3) * 2;
            *reinterpret_cast<float2*>(g_HW + (size_t)row * D + col) =
                make_float2(acc[mt][nt][0], acc[mt][nt][1]);
            *reinterpret_cast<float2*>(g_HW + (size_t)(row + 8) * D + col) =
                make_float2(acc[mt][nt][2], acc[mt][nt][3]);
        }
    }

    // logit partials: lp[tile][row] = sum_col H[row][col] * a[col]
    {
        float* lpb = reinterpret_cast<float*>(sm);   // [64][4][2]
        #pragma unroll
        for (int mt = 0; mt < 2; mt++)
            #pragma unroll
            for (int half = 0; half < 2; half++) {
                int rl = wm + mt * 16 + (lane >> 2) + half * 8;
                float s = 0.f, t = 0.f;
                #pragma unroll
                for (int nt = 0; nt < 2; nt++) {
                    int col = n0 + wn + nt * 8 + (lane & 3) * 2;
                    float v0 = acc[mt][nt][half * 2], v1 = acc[mt][nt][half * 2 + 1];
                    s += v0 * asrc[col] + v1 * asrc[col + 1];
                    t += v0 * adst[col] + v1 * adst[col + 1];
                }
                s += __shfl_xor_sync(0xffffffffu, s, 1);
                s += __shfl_xor_sync(0xffffffffu, s, 2);
                t += __shfl_xor_sync(0xffffffffu, t, 1);
                t += __shfl_xor_sync(0xffffffffu, t, 2);
                if ((lane & 3) == 0) {
                    lpb[(rl * 4 + (wid & 3)) * 2 + 0] = s;
                    lpb[(rl * 4 + (wid & 3)) * 2 + 1] = t;
                }
            }
        __syncthreads();
        if (tid < 128) {
            int rl = tid >> 1, comp = tid & 1;
            int row = m0 + rl;
            if (row < NN) {
                float s = lpb[(rl * 4 + 0) * 2 + comp] + lpb[(rl * 4 + 1) * 2 + comp]
                        + lpb[(rl * 4 + 2) * 2 + comp] + lpb[(rl * 4 + 3) * 2 + comp];
                g_lp[n0 >> 6][row][comp] = s;
            }
        }
        __syncthreads();
    }

    // transpose via smem, write Ht bf16 split
    float* ts = reinterpret_cast<float*>(sm);   // [64][65]
    #pragma unroll
    for (int mt = 0; mt < 2; mt++)
        #pragma unroll
        for (int nt = 0; nt < 2; nt++)
            #pragma unroll
            for (int j = 0; j < 4; j++) {
                int rl = wm + mt * 16 + (lane >> 2) + (j >> 1) * 8;
                int cl = wn + nt * 8 + (lane & 3) * 2 + (j & 1);
                ts[rl * 65 + cl] = acc[mt][nt][j];
            }
    __syncthreads();
    #pragma unroll
    for (int it = 0; it < 16; it++) {
        int lin = it * 256 + tid;
        int n = lin >> 6, m = lin & 63;
        __nv_bfloat16 hi, lo;
        bsplit(ts[m * 65 + n], hi, lo);
        g_Hth[(size_t)(n0 + n) * MPAD + m0 + m] = hi;
        g_Htl[(size_t)(n0 + n) * MPAD + m0 + m] = lo;
    }
}

// ============================ alpha (from g_lp; no max subtraction) ============================
// blocks 0..127: samples (8 warps, 1 each). layer 1 only: 128..227 proxies, 228..255 zero pads.
__global__ void k_alpha(int layer) {
    int tid = threadIdx.x;
    int b = blockIdx.x;
    if (b < 128) {
        __shared__ float lsp[128];
        if (tid < NP) {
            float s = 0.f;
            #pragma unroll
            for (int ti = 0; ti < 8; ti++) s += g_lp[ti][tid][0];
            lsp[tid] = s;
        }
        __syncthreads();
        int warp = b * 8 + (tid >> 5);
        int lane = tid & 31;
        int node = NP + warp;
        float lsn = 0.f, ldn = 0.f;
        #pragma unroll
        for (int ti = 0; ti < 8; ti++) {
            lsn += g_lp[ti][node][0];
            ldn += g_lp[ti][node][1];
        }
        float w[4], sum = 0.f;
        #pragma unroll
        for (int i = 0; i < 4; i++) {
            int p = lane + 32 * i;
            w[i] = (p < NP) ? __expf(lrelu(lsp[p] + ldn)) : 0.f;
            sum += w[i];
        }
        float wself = __expf(lrelu(lsn + ldn));
        #pragma unroll
        for (int o = 16; o > 0; o >>= 1) sum += __shfl_xor_sync(0xffffffffu, sum, o);
        float inv = 1.f / (sum + wself);
        #pragma unroll
        for (int i = 0; i < 4; i++) {
            int p = lane + 32 * i;
            __nv_bfloat16 hi, lo;
            bsplit(w[i] * inv, hi, lo);
            g_aSh[(size_t)warp * KPAD2 + p] = hi;
            g_aSl[(size_t)warp * KPAD2 + p] = lo;
        }
        if (lane == 0) g_aselfS[warp] = wself * inv;
    } else if (b < 228) {
        __shared__ float sh[8];
        __shared__ float s_inv;
        int p = b - 128;
        float ldp = 0.f, lspp = 0.f;
        #pragma unroll
        for (int ti = 0; ti < 8; ti++) {
            ldp += g_lp[ti][p][1];
            lspp += g_lp[ti][p][0];
        }
        float w[4], sum = 0.f;
        #pragma unroll
        for (int i = 0; i < 4; i++) {
            int s = tid + i * 256;
            float ls = 0.f;
            #pragma unroll
            for (int ti = 0; ti < 8; ti++) ls += g_lp[ti][NP + s][0];
            w[i] = __expf(lrelu(ls + ldp));
            sum += w[i];
        }
        float wself = __expf(lrelu(lspp + ldp));
        #pragma unroll
        for (int o = 16; o > 0; o >>= 1) sum += __shfl_xor_sync(0xffffffffu, sum, o);
        if ((tid & 31) == 0) sh[tid >> 5] = sum;
        __syncthreads();
        if (tid == 0) {
            float ss = 0.f;
            #pragma unroll
            for (int i = 0; i < 8; i++) ss += sh[i];
            s_inv = 1.f / (ss + wself);
        }
        __syncthreads();
        float inv = s_inv;
        #pragma unroll
        for (int i = 0; i < 4; i++) {
            int col = NP + tid + i * 256;
            __nv_bfloat16 hi, lo;
            bsplit(w[i] * inv, hi, lo);
            g_aPh[(size_t)p * MPAD + col] = hi;
            g_aPl[(size_t)p * MPAD + col] = lo;
        }
        // cols 0..99: zero except self on the diagonal
        if (tid < NP) {
            float dv = (tid == p) ? wself * inv : 0.f;
            __nv_bfloat16 hi, lo;
            bsplit(dv, hi, lo);
            g_aPh[(size_t)p * MPAD + tid] = hi;
            g_aPl[(size_t)p * MPAD + tid] = lo;
        }
        if (tid < MPAD - NN) {
            __nv_bfloat16 z = __float2bfloat16(0.f);
            g_aPh[(size_t)p * MPAD + NN + tid] = z;
            g_aPl[(size_t)p * MPAD + NN + tid] = z;
        }
    } else {
        int p = 100 + (b - 228);
        uint32_t* h = reinterpret_cast<uint32_t*>(g_aPh + (size_t)p * MPAD);
        uint32_t* l = reinterpret_cast<uint32_t*>(g_aPl + (size_t)p * MPAD);
        for (int i = tid; i < MPAD / 2; i += 256) { h[i] = 0u; l[i] = 0u; }
    }
}

// ============================ aggregation GEMM (tensor cores) ============================
// layer 1, grid 144: blocks 0..127 sample tiles; 128..143 proxy tiles (K=1152, self on diag).
// layer 2, grid 128: sample tiles only (also writes fp32 h output).
__global__ void __launch_bounds__(256, 1) k_aggm(const float* __restrict__ bias,
                                                 float* __restrict__ hout, int layer) {
    extern __shared__ __align__(16) char sm[];
    int tid = threadIdx.x, wid = tid >> 5, lane = tid & 31;
    int wm = (wid >> 2) * 32, wn = (wid & 3) * 16;
    uint32_t sb = smem_u32(sm);
    int b = blockIdx.x;

    if (b < 128) {
        int m0 = (b >> 3) * 64, n0 = (b & 7) * 64;
        MMA_MAINLOOP(g_aSh, g_aSl, g_Hth, g_Htl, KPAD2, MPAD, 2)
        #pragma unroll
        for (int mt = 0; mt < 2; mt++)
            #pragma unroll
            for (int nt = 0; nt < 2; nt++)
                #pragma unroll
                for (int j = 0; j < 4; j++) {
                    int r = m0 + wm + mt * 16 + (lane >> 2) + (j >> 1) * 8;
                    int col = n0 + wn + nt * 8 + (lane & 3) * 2 + (j & 1);
                    float v = acc[mt][nt][j] + g_aselfS[r] * g_HW[(size_t)(NP + r) * D + col]
                            + bias[col];
                    acc[mt][nt][j] = v > 0.f ? v : 0.f;
                }
        #pragma unroll
        for (int mt = 0; mt < 2; mt++)
            #pragma unroll
            for (int half = 0; half < 2; half++) {
                int r = m0 + wm + mt * 16 + (lane >> 2) + half * 8;
                int arow = (layer == 1) ? (NP + r) : r;
                #pragma unroll
                for (int nt = 0; nt < 2; nt++) {
                    int col = n0 + wn + nt * 8 + (lane & 3) * 2;
                    float v0 = acc[mt][nt][half * 2], v1 = acc[mt][nt][half * 2 + 1];
                    __nv_bfloat16 h0, h1, l0, l1;
                    bsplit(v0, h0, l0); bsplit(v1, h1, l1);
                    *reinterpret_cast<__nv_bfloat162*>(g_Ah + (size_t)arow * D + col) =
                        __nv_bfloat162(h0, h1);
                    *reinterpret_cast<__nv_bfloat162*>(g_Al + (size_t)arow * D + col) =
                        __nv_bfloat162(l0, l1);
                    if (layer == 2)
                        *reinterpret_cast<float2*>(hout + (size_t)r * D + col) =
                            make_float2(v0, v1);
                }
            }
    } else {
        int bb = b - 128;
        int m0 = (bb >> 3) * 64, n0 = (bb & 7) * 64;
        MMA_MAINLOOP(g_aPh, g_aPl, g_Hth, g_Htl, MPAD, MPAD, 18)
        #pragma unroll
        for (int mt = 0; mt < 2; mt++)
            #pragma unroll
            for (int half = 0; half < 2; half++) {
                int p = m0 + wm + mt * 16 + (lane >> 2) + half * 8;
                if (p >= NP) continue;
                #pragma unroll
                for (int nt = 0; nt < 2; nt++) {
                    int col = n0 + wn + nt * 8 + (lane & 3) * 2;
                    float v0 = acc[mt][nt][half * 2] + bias[col];
                    float v1 = acc[mt][nt][half * 2 + 1] + bias[col + 1];
                    v0 = v0 > 0.f ? v0 : 0.f;
                    v1 = v1 > 0.f ? v1 : 0.f;
                    __nv_bfloat16 h0, h1, l0, l1;
                    bsplit(v0, h0, l0); bsplit(v1, h1, l1);
                    *reinterpret_cast<__nv_bfloat162*>(g_Ah + (size_t)p * D + col) =
                        __nv_bfloat162(h0, h1);
                    *reinterpret_cast<__nv_bfloat162*>(g_Al + (size_t)p * D + col) =
                        __nv_bfloat162(l0, l1);
                }
            }
    }
}

// ============================ launch ============================
extern "C" void kernel_launch(void* const* d_in, const int* in_sizes, int n_in,
                              void* d_out, int out_size) {
    const float* x    = (const float*)d_in[0];
    const float* prox = (const float*)d_in[1];
    const float* W1   = (const float*)d_in[2];
    const float* as1  = (const float*)d_in[3];
    const float* ad1  = (const float*)d_in[4];
    const float* b1   = (const float*)d_in[5];
    const float* W2   = (const float*)d_in[6];
    const float* as2  = (const float*)d_in[7];
    const float* ad2  = (const float*)d_in[8];
    const float* b2   = (const float*)d_in[9];
    const float* fcw  = (const float*)d_in[10];
    const float* fcb  = (const float*)d_in[11];
    float* out = (float*)d_out;

    __nv_bfloat16 *pAh, *pAl, *pW1h, *pW1l, *pW2h, *pW2l, *pFCh, *pFCl;
    cudaGetSymbolAddress((void**)&pAh,  g_Ah);
    cudaGetSymbolAddress((void**)&pAl,  g_Al);
    cudaGetSymbolAddress((void**)&pW1h, g_W1h);
    cudaGetSymbolAddress((void**)&pW1l, g_W1l);
    cudaGetSymbolAddress((void**)&pW2h, g_W2h);
    cudaGetSymbolAddress((void**)&pW2l, g_W2l);
    cudaGetSymbolAddress((void**)&pFCh, g_FCh);
    cudaGetSymbolAddress((void**)&pFCl, g_FCl);

    cudaFuncSetAttribute(k_mma,  cudaFuncAttributeMaxDynamicSharedMemorySize, 2 * STAGE_BYTES);
    cudaFuncSetAttribute(k_aggm, cudaFuncAttributeMaxDynamicSharedMemorySize, 2 * STAGE_BYTES);

    k_setup<<<1152, 256>>>(W1, W2, fcw, x, prox);

    // ---- layer 1
    k_mma<<<dim3(8, 18), 256, 2 * STAGE_BYTES>>>(pAh, pAl, pW1h, pW1l, nullptr, nullptr, 1, as1, ad1);
    k_alpha<<<256, 256>>>(1);
    k_aggm<<<144, 256, 2 * STAGE_BYTES>>>(b1, nullptr, 1);

    // ---- layer 2 (proxy aggregation unused downstream)
    k_mma<<<dim3(8, 18), 256, 2 * STAGE_BYTES>>>(pAh, pAl, pW2h, pW2l, nullptr, nullptr, 1, as2, ad2);
    k_alpha<<<128, 256>>>(2);
    k_aggm<<<128, 256, 2 * STAGE_BYTES>>>(b2, out + NS * 100, 2);

    // ---- preds = h @ fc_w + fc_b
    k_mma<<<dim3(2, 16), 256, 2 * STAGE_BYTES>>>(pAh, pAl, pFCh, pFCl, out, fcb, 0, nullptr, nullptr);
}

// round 10
// speedup vs baseline: 1.3134x; 1.1332x over previous
#include <cuda_runtime.h>
#include <cuda_bf16.h>
#include <cstdint>

#define NP 100      // proxies
#define NS 1024     // samples
#define NN 1124     // total nodes
#define MPAD 1152   // NN padded to 128
#define D  512
#define KPAD2 128   // NP padded for sample-agg K
#define PSPLIT 9    // proxy-agg split-K factor (9 x 128 = 1152)

// scratch (device globals; no allocation allowed)
__device__ float g_HW[MPAD * D];
__device__ float g_aselfS[NS];
__device__ float g_lp[8][NN][2];        // logit partials [64col-tile][node][src/dst]
__device__ float g_ppart[PSPLIT][128][D];
// bf16 split operands
__device__ __nv_bfloat16 g_Ah[MPAD * D];
__device__ __nv_bfloat16 g_Al[MPAD * D];
__device__ __nv_bfloat16 g_W1h[D * D];
__device__ __nv_bfloat16 g_W1l[D * D];
__device__ __nv_bfloat16 g_W2h[D * D];
__device__ __nv_bfloat16 g_W2l[D * D];
__device__ __nv_bfloat16 g_FCh[128 * D];
__device__ __nv_bfloat16 g_FCl[128 * D];
__device__ __nv_bfloat16 g_Hth[D * MPAD];   // H transposed [d][node]
__device__ __nv_bfloat16 g_Htl[D * MPAD];
__device__ __nv_bfloat16 g_aSh[NS * KPAD2]; // alpha (sample dst), K-major
__device__ __nv_bfloat16 g_aSl[NS * KPAD2];
__device__ __nv_bfloat16 g_aPh[128 * MPAD]; // alpha (proxy dst), K over all nodes, self on diag
__device__ __nv_bfloat16 g_aPl[128 * MPAD];

__device__ __forceinline__ float lrelu(float v) { return v > 0.f ? v : 0.2f * v; }

__device__ __forceinline__ uint32_t smem_u32(const void* p) {
    uint32_t a;
    asm("{ .reg .u64 t; cvta.to.shared.u64 t, %1; cvt.u32.u64 %0, t; }" : "=r"(a) : "l"(p));
    return a;
}
__device__ __forceinline__ void bsplit(float v, __nv_bfloat16& hi, __nv_bfloat16& lo) {
    hi = __float2bfloat16(v);
    lo = __float2bfloat16(v - __bfloat162float(hi));
}

// ============================ setup: W splits + input convert ============================
__global__ void k_setup(const float* __restrict__ W1, const float* __restrict__ W2,
                        const float* __restrict__ fcw,
                        const float* __restrict__ x, const float* __restrict__ prox) {
    int b = blockIdx.x;
    if (b < 512) {
        const float* W = (b >= 256) ? W2 : W1;
        __nv_bfloat16* Wh = (b >= 256) ? g_W2h : g_W1h;
        __nv_bfloat16* Wl = (b >= 256) ? g_W2l : g_W1l;
        int bb = b & 255;
        __shared__ float t[32][33];
        int tx = threadIdx.x & 31, ty = threadIdx.x >> 5;
        int n0 = (bb & 15) * 32, k0 = (bb >> 4) * 32;
        #pragma unroll
        for (int j = 0; j < 4; j++)
            t[ty + 8 * j][tx] = W[(size_t)(k0 + ty + 8 * j) * D + n0 + tx];
        __syncthreads();
        #pragma unroll
        for (int j = 0; j < 4; j++) {
            int n = n0 + ty + 8 * j, k = k0 + tx;
            __nv_bfloat16 hi, lo;
            bsplit(t[tx][ty + 8 * j], hi, lo);
            Wh[(size_t)n * D + k] = hi;
            Wl[(size_t)n * D + k] = lo;
        }
    } else if (b < 576) {
        int bb = b - 512;
        __shared__ float t[32][33];
        int tx = threadIdx.x & 31, ty = threadIdx.x >> 5;
        int n0 = (bb & 3) * 32, k0 = (bb >> 2) * 32;
        #pragma unroll
        for (int j = 0; j < 4; j++) {
            int n = n0 + tx;
            t[ty + 8 * j][tx] = (n < 100) ? fcw[(size_t)(k0 + ty + 8 * j) * 100 + n] : 0.f;
        }
        __syncthreads();
        #pragma unroll
        for (int j = 0; j < 4; j++) {
            int n = n0 + ty + 8 * j, k = k0 + tx;
            __nv_bfloat16 hi, lo;
            bsplit(t[tx][ty + 8 * j], hi, lo);
            g_FCh[(size_t)n * D + k] = hi;
            g_FCl[(size_t)n * D + k] = lo;
        }
    } else {
        int row = (b - 576) * 2 + (threadIdx.x >> 7);
        int c4 = (threadIdx.x & 127) * 4;
        int base = row * D + c4;
        float4 v = make_float4(0.f, 0.f, 0.f, 0.f);
        if (row < NP)      v = *reinterpret_cast<const float4*>(prox + base);
        else if (row < NN) v = *reinterpret_cast<const float4*>(x + base - NP * D);
        __nv_bfloat16 h0, h1, h2, h3, l0, l1, l2, l3;
        bsplit(v.x, h0, l0); bsplit(v.y, h1, l1); bsplit(v.z, h2, l2); bsplit(v.w, h3, l3);
        *reinterpret_cast<__nv_bfloat162*>(g_Ah + base)     = __nv_bfloat162(h0, h1);
        *reinterpret_cast<__nv_bfloat162*>(g_Ah + base + 2) = __nv_bfloat162(h2, h3);
        *reinterpret_cast<__nv_bfloat162*>(g_Al + base)     = __nv_bfloat162(l0, l1);
        *reinterpret_cast<__nv_bfloat162*>(g_Al + base + 2) = __nv_bfloat162(l2, l3);
    }
}

// ============================ mma common ============================
#define SWB(r, b) ((r) * 128 + ((b) ^ (((r) & 7) << 4)))
#define STAGE_BYTES 32768

__device__ __forceinline__ void ldm_x4(uint32_t* f, uint32_t addr) {
    asm volatile("ldmatrix.sync.aligned.m8n8.x4.shared.b16 {%0,%1,%2,%3}, [%4];"
                 : "=r"(f[0]), "=r"(f[1]), "=r"(f[2]), "=r"(f[3]) : "r"(addr));
}
__device__ __forceinline__ void ldm_x2(uint32_t* f, uint32_t addr) {
    asm volatile("ldmatrix.sync.aligned.m8n8.x2.shared.b16 {%0,%1}, [%2];"
                 : "=r"(f[0]), "=r"(f[1]) : "r"(addr));
}
__device__ __forceinline__ void mma_bf16(float* c, const uint32_t* a, const uint32_t* b) {
    asm volatile(
        "mma.sync.aligned.m16n8k16.row.col.f32.bf16.bf16.f32 "
        "{%0,%1,%2,%3}, {%4,%5,%6,%7}, {%8,%9}, {%0,%1,%2,%3};"
        : "+f"(c[0]), "+f"(c[1]), "+f"(c[2]), "+f"(c[3])
        : "r"(a[0]), "r"(a[1]), "r"(a[2]), "r"(a[3]), "r"(b[0]), "r"(b[1]));
}
__device__ __forceinline__ void cpa16(uint32_t saddr, const void* g) {
    asm volatile("cp.async.cg.shared.global [%0], [%1], 16;" :: "r"(saddr), "l"(g));
}

#define MMA_MAINLOOP(AH, AL, BH, BL, LDA, LDB, NCHUNK, KOFF)                             \
    int li = tid * 2;                                                                    \
    int lr0 = li >> 3, ls0 = li & 7;                                                     \
    int lr1 = (li + 1) >> 3, ls1 = (li + 1) & 7;                                         \
    int a_r = (lane & 7) + ((lane >> 3) & 1) * 8;                                        \
    int a_kb = (lane >> 4) * 16;                                                         \
    int b_r = lane & 7;                                                                  \
    int b_kb = ((lane >> 3) & 1) * 16;                                                   \
    float acc[2][2][4] = {};                                                             \
    auto issue = [&](int c, int st) {                                                    \
        int kc = (KOFF) + c * 64;                                                        \
        uint32_t stb = sb + st * STAGE_BYTES;                                            \
        cpa16(stb + SWB(lr0, ls0 * 16), (AH) + (size_t)(m0 + lr0) * (LDA) + kc + ls0 * 8); \
        cpa16(stb + SWB(lr1, ls1 * 16), (AH) + (size_t)(m0 + lr1) * (LDA) + kc + ls1 * 8); \
        cpa16(stb + 8192 + SWB(lr0, ls0 * 16), (AL) + (size_t)(m0 + lr0) * (LDA) + kc + ls0 * 8); \
        cpa16(stb + 8192 + SWB(lr1, ls1 * 16), (AL) + (size_t)(m0 + lr1) * (LDA) + kc + ls1 * 8); \
        cpa16(stb + 16384 + SWB(lr0, ls0 * 16), (BH) + (size_t)(n0 + lr0) * (LDB) + kc + ls0 * 8); \
        cpa16(stb + 16384 + SWB(lr1, ls1 * 16), (BH) + (size_t)(n0 + lr1) * (LDB) + kc + ls1 * 8); \
        cpa16(stb + 24576 + SWB(lr0, ls0 * 16), (BL) + (size_t)(n0 + lr0) * (LDB) + kc + ls0 * 8); \
        cpa16(stb + 24576 + SWB(lr1, ls1 * 16), (BL) + (size_t)(n0 + lr1) * (LDB) + kc + ls1 * 8); \
        asm volatile("cp.async.commit_group;");                                          \
    };                                                                                   \
    issue(0, 0);                                                                         \
    asm volatile("cp.async.wait_group 0;");                                              \
    __syncthreads();                                                                     \
    for (int c = 0; c < (NCHUNK); c++) {                                                 \
        int st = c & 1;                                                                  \
        if (c + 1 < (NCHUNK)) issue(c + 1, st ^ 1);                                      \
        uint32_t stb = sb + st * STAGE_BYTES;                                            \
        _Pragma("unroll")                                                                \
        for (int ks = 0; ks < 4; ks++) {                                                 \
            int kb = ks * 32;                                                            \
            uint32_t ah[2][4], al[2][4], bh[2][2], bl[2][2];                             \
            _Pragma("unroll")                                                            \
            for (int mt = 0; mt < 2; mt++) {                                             \
                int r = wm + mt * 16 + a_r;                                              \
                ldm_x4(ah[mt], stb + 0    + SWB(r, kb + a_kb));                          \
                ldm_x4(al[mt], stb + 8192 + SWB(r, kb + a_kb));                          \
            }                                                                            \
            _Pragma("unroll")                                                            \
            for (int nt = 0; nt < 2; nt++) {                                             \
                int r = wn + nt * 8 + b_r;                                               \
                ldm_x2(bh[nt], stb + 16384 + SWB(r, kb + b_kb));                         \
                ldm_x2(bl[nt], stb + 24576 + SWB(r, kb + b_kb));                         \
            }                                                                            \
            _Pragma("unroll")                                                            \
            for (int mt = 0; mt < 2; mt++)                                               \
                _Pragma("unroll")                                                        \
                for (int nt = 0; nt < 2; nt++) {                                         \
                    mma_bf16(acc[mt][nt], ah[mt], bh[nt]);                               \
                    mma_bf16(acc[mt][nt], ah[mt], bl[nt]);                               \
                    mma_bf16(acc[mt][nt], al[mt], bh[nt]);                               \
                }                                                                        \
        }                                                                                \
        if (c + 1 < (NCHUNK)) asm volatile("cp.async.wait_group 0;");                    \
        __syncthreads();                                                                 \
    }

// ============================ layer GEMM / FC GEMM ============================
// mode 0: FC -> C fp32 (ldc=100, col guard) + bias.
// mode 1: H = A@W -> g_HW fp32 + g_lp logit partials + Ht bf16 split.
__global__ void __launch_bounds__(256, 1) k_mma(
    const __nv_bfloat16* __restrict__ Ah, const __nv_bfloat16* __restrict__ Al,
    const __nv_bfloat16* __restrict__ Bh, const __nv_bfloat16* __restrict__ Bl,
    float* __restrict__ C, const float* __restrict__ bias, int mode,
    const float* __restrict__ asrc, const float* __restrict__ adst) {
    extern __shared__ __align__(16) char sm[];
    int tid = threadIdx.x, wid = tid >> 5, lane = tid & 31;
    int n0 = blockIdx.x * 64, m0 = blockIdx.y * 64;
    int wm = (wid >> 2) * 32, wn = (wid & 3) * 16;
    uint32_t sb = smem_u32(sm);

    MMA_MAINLOOP(Ah, Al, Bh, Bl, D, D, 8, 0)

    if (mode == 0) {
        #pragma unroll
        for (int mt = 0; mt < 2; mt++) {
            int row = m0 + wm + mt * 16 + (lane >> 2);
            #pragma unroll
            for (int nt = 0; nt < 2; nt++) {
                int col = n0 + wn + nt * 8 + (lane & 3) * 2;
                if (col >= 100) continue;
                float b0 = bias[col], b1 = bias[col + 1];
                *reinterpret_cast<float2*>(C + (size_t)row * 100 + col) =
                    make_float2(acc[mt][nt][0] + b0, acc[mt][nt][1] + b1);
                *reinterpret_cast<float2*>(C + (size_t)(row + 8) * 100 + col) =
                    make_float2(acc[mt][nt][2] + b0, acc[mt][nt][3] + b1);
            }
        }
        return;
    }

    // fp32 HW store
    #pragma unroll
    for (int mt = 0; mt < 2; mt++) {
        int row = m0 + wm + mt * 16 + (lane >> 2);
        #pragma unroll
        for (int nt = 0; nt < 2; nt++) {
            int col = n0 + wn + nt * 8 + (lane & 3) * 2;
            *reinterpret_cast<float2*>(g_HW + (size_t)row * D + col) =
                make_float2(acc[mt][nt][0], acc[mt][nt][1]);
            *reinterpret_cast<float2*>(g_HW + (size_t)(row + 8) * D + col) =
                make_float2(acc[mt][nt][2], acc[mt][nt][3]);
        }
    }

    // logit partials
    {
        float* lpb = reinterpret_cast<float*>(sm);   // [64][4][2]
        #pragma unroll
        for (int mt = 0; mt < 2; mt++)
            #pragma unroll
            for (int half = 0; half < 2; half++) {
                int rl = wm + mt * 16 + (lane >> 2) + half * 8;
                float s = 0.f, t = 0.f;
                #pragma unroll
                for (int nt = 0; nt < 2; nt++) {
                    int col = n0 + wn + nt * 8 + (lane & 3) * 2;
                    float v0 = acc[mt][nt][half * 2], v1 = acc[mt][nt][half * 2 + 1];
                    s += v0 * asrc[col] + v1 * asrc[col + 1];
                    t += v0 * adst[col] + v1 * adst[col + 1];
                }
                s += __shfl_xor_sync(0xffffffffu, s, 1);
                s += __shfl_xor_sync(0xffffffffu, s, 2);
                t += __shfl_xor_sync(0xffffffffu, t, 1);
                t += __shfl_xor_sync(0xffffffffu, t, 2);
                if ((lane & 3) == 0) {
                    lpb[(rl * 4 + (wid & 3)) * 2 + 0] = s;
                    lpb[(rl * 4 + (wid & 3)) * 2 + 1] = t;
                }
            }
        __syncthreads();
        if (tid < 128) {
            int rl = tid >> 1, comp = tid & 1;
            int row = m0 + rl;
            if (row < NN) {
                float s = lpb[(rl * 4 + 0) * 2 + comp] + lpb[(rl * 4 + 1) * 2 + comp]
                        + lpb[(rl * 4 + 2) * 2 + comp] + lpb[(rl * 4 + 3) * 2 + comp];
                g_lp[n0 >> 6][row][comp] = s;
            }
        }
        __syncthreads();
    }

    // transpose via smem, write Ht bf16 split
    float* ts = reinterpret_cast<float*>(sm);   // [64][65]
    #pragma unroll
    for (int mt = 0; mt < 2; mt++)
        #pragma unroll
        for (int nt = 0; nt < 2; nt++)
            #pragma unroll
            for (int j = 0; j < 4; j++) {
                int rl = wm + mt * 16 + (lane >> 2) + (j >> 1) * 8;
                int cl = wn + nt * 8 + (lane & 3) * 2 + (j & 1);
                ts[rl * 65 + cl] = acc[mt][nt][j];
            }
    __syncthreads();
    #pragma unroll
    for (int it = 0; it < 16; it++) {
        int lin = it * 256 + tid;
        int n = lin >> 6, m = lin & 63;
        __nv_bfloat16 hi, lo;
        bsplit(ts[m * 65 + n], hi, lo);
        g_Hth[(size_t)(n0 + n) * MPAD + m0 + m] = hi;
        g_Htl[(size_t)(n0 + n) * MPAD + m0 + m] = lo;
    }
}

// ============================ alpha (from g_lp; no max subtraction) ============================
__global__ void k_alpha(int layer) {
    int tid = threadIdx.x;
    int b = blockIdx.x;
    if (b < 128) {
        __shared__ float lsp[128];
        if (tid < NP) {
            float s = 0.f;
            #pragma unroll
            for (int ti = 0; ti < 8; ti++) s += g_lp[ti][tid][0];
            lsp[tid] = s;
        }
        __syncthreads();
        int warp = b * 8 + (tid >> 5);
        int lane = tid & 31;
        int node = NP + warp;
        float lsn = 0.f, ldn = 0.f;
        #pragma unroll
        for (int ti = 0; ti < 8; ti++) {
            lsn += g_lp[ti][node][0];
            ldn += g_lp[ti][node][1];
        }
        float w[4], sum = 0.f;
        #pragma unroll
        for (int i = 0; i < 4; i++) {
            int p = lane + 32 * i;
            w[i] = (p < NP) ? __expf(lrelu(lsp[p] + ldn)) : 0.f;
            sum += w[i];
        }
        float wself = __expf(lrelu(lsn + ldn));
        #pragma unroll
        for (int o = 16; o > 0; o >>= 1) sum += __shfl_xor_sync(0xffffffffu, sum, o);
        float inv = 1.f / (sum + wself);
        #pragma unroll
        for (int i = 0; i < 4; i++) {
            int p = lane + 32 * i;
            __nv_bfloat16 hi, lo;
            bsplit(w[i] * inv, hi, lo);
            g_aSh[(size_t)warp * KPAD2 + p] = hi;
            g_aSl[(size_t)warp * KPAD2 + p] = lo;
        }
        if (lane == 0) g_aselfS[warp] = wself * inv;
    } else if (b < 228) {
        __shared__ float sh[8];
        __shared__ float s_inv;
        int p = b - 128;
        float ldp = 0.f, lspp = 0.f;
        #pragma unroll
        for (int ti = 0; ti < 8; ti++) {
            ldp += g_lp[ti][p][1];
            lspp += g_lp[ti][p][0];
        }
        float w[4], sum = 0.f;
        #pragma unroll
        for (int i = 0; i < 4; i++) {
            int s = tid + i * 256;
            float ls = 0.f;
            #pragma unroll
            for (int ti = 0; ti < 8; ti++) ls += g_lp[ti][NP + s][0];
            w[i] = __expf(lrelu(ls + ldp));
            sum += w[i];
        }
        float wself = __expf(lrelu(lspp + ldp));
        #pragma unroll
        for (int o = 16; o > 0; o >>= 1) sum += __shfl_xor_sync(0xffffffffu, sum, o);
        if ((tid & 31) == 0) sh[tid >> 5] = sum;
        __syncthreads();
        if (tid == 0) {
            float ss = 0.f;
            #pragma unroll
            for (int i = 0; i < 8; i++) ss += sh[i];
            s_inv = 1.f / (ss + wself);
        }
        __syncthreads();
        float inv = s_inv;
        #pragma unroll
        for (int i = 0; i < 4; i++) {
            int col = NP + tid + i * 256;
            __nv_bfloat16 hi, lo;
            bsplit(w[i] * inv, hi, lo);
            g_aPh[(size_t)p * MPAD + col] = hi;
            g_aPl[(size_t)p * MPAD + col] = lo;
        }
        if (tid < NP) {
            float dv = (tid == p) ? wself * inv : 0.f;
            __nv_bfloat16 hi, lo;
            bsplit(dv, hi, lo);
            g_aPh[(size_t)p * MPAD + tid] = hi;
            g_aPl[(size_t)p * MPAD + tid] = lo;
        }
        if (tid < MPAD - NN) {
            __nv_bfloat16 z = __float2bfloat16(0.f);
            g_aPh[(size_t)p * MPAD + NN + tid] = z;
            g_aPl[(size_t)p * MPAD + NN + tid] = z;
        }
    } else {
        int p = 100 + (b - 228);
        uint32_t* h = reinterpret_cast<uint32_t*>(g_aPh + (size_t)p * MPAD);
        uint32_t* l = reinterpret_cast<uint32_t*>(g_aPl + (size_t)p * MPAD);
        for (int i = tid; i < MPAD / 2; i += 256) { h[i] = 0u; l[i] = 0u; }
    }
}

// ============================ aggregation GEMM (tensor cores) ============================
// blocks 0..127 sample tiles (K=128).
// layer 1 only: blocks 128..271 proxy tiles x split-K (16 tiles x 9 splits, 2 chunks each).
__global__ void __launch_bounds__(256, 1) k_aggm(const float* __restrict__ bias,
                                                 float* __restrict__ hout, int layer) {
    extern __shared__ __align__(16) char sm[];
    int tid = threadIdx.x, wid = tid >> 5, lane = tid & 31;
    int wm = (wid >> 2) * 32, wn = (wid & 3) * 16;
    uint32_t sb = smem_u32(sm);
    int b = blockIdx.x;

    if (b < 128) {
        int m0 = (b >> 3) * 64, n0 = (b & 7) * 64;
        MMA_MAINLOOP(g_aSh, g_aSl, g_Hth, g_Htl, KPAD2, MPAD, 2, 0)
        #pragma unroll
        for (int mt = 0; mt < 2; mt++)
            #pragma unroll
            for (int nt = 0; nt < 2; nt++)
                #pragma unroll
                for (int j = 0; j < 4; j++) {
                    int r = m0 + wm + mt * 16 + (lane >> 2) + (j >> 1) * 8;
                    int col = n0 + wn + nt * 8 + (lane & 3) * 2 + (j & 1);
                    float v = acc[mt][nt][j] + g_aselfS[r] * g_HW[(size_t)(NP + r) * D + col]
                            + bias[col];
                    acc[mt][nt][j] = v > 0.f ? v : 0.f;
                }
        #pragma unroll
        for (int mt = 0; mt < 2; mt++)
            #pragma unroll
            for (int half = 0; half < 2; half++) {
                int r = m0 + wm + mt * 16 + (lane >> 2) + half * 8;
                int arow = (layer == 1) ? (NP + r) : r;
                #pragma unroll
                for (int nt = 0; nt < 2; nt++) {
                    int col = n0 + wn + nt * 8 + (lane & 3) * 2;
                    float v0 = acc[mt][nt][half * 2], v1 = acc[mt][nt][half * 2 + 1];
                    __nv_bfloat16 h0, h1, l0, l1;
                    bsplit(v0, h0, l0); bsplit(v1, h1, l1);
                    *reinterpret_cast<__nv_bfloat162*>(g_Ah + (size_t)arow * D + col) =
                        __nv_bfloat162(h0, h1);
                    *reinterpret_cast<__nv_bfloat162*>(g_Al + (size_t)arow * D + col) =
                        __nv_bfloat162(l0, l1);
                    if (layer == 2)
                        *reinterpret_cast<float2*>(hout + (size_t)r * D + col) =
                            make_float2(v0, v1);
                }
            }
    } else {
        int bb = b - 128;
        int tile = bb & 15;
        int z = bb >> 4;                       // split index 0..8
        int m0 = (tile >> 3) * 64, n0 = (tile & 7) * 64;
        MMA_MAINLOOP(g_aPh, g_aPl, g_Hth, g_Htl, MPAD, MPAD, 2, z * 128)
        float* part = &g_ppart[z][0][0];
        #pragma unroll
        for (int mt = 0; mt < 2; mt++)
            #pragma unroll
            for (int half = 0; half < 2; half++) {
                int p = m0 + wm + mt * 16 + (lane >> 2) + half * 8;
                if (p >= NP) continue;
                #pragma unroll
                for (int nt = 0; nt < 2; nt++) {
                    int col = n0 + wn + nt * 8 + (lane & 3) * 2;
                    *reinterpret_cast<float2*>(part + (size_t)p * D + col) =
                        make_float2(acc[mt][nt][half * 2], acc[mt][nt][half * 2 + 1]);
                }
            }
    }
}

// proxy finalize: sum 9 split-K partials + bias, relu -> bf16 split rows 0..99 of g_Ah/g_Al
__global__ void k_pfin(const float* __restrict__ bias) {
    int idx = blockIdx.x * 256 + threadIdx.x;   // over NP*D/2 float2 elems
    int p = idx / (D / 2);
    int c = (idx - p * (D / 2)) * 2;
    float v0 = 0.f, v1 = 0.f;
    #pragma unroll
    for (int z = 0; z < PSPLIT; z++) {
        float2 t = *reinterpret_cast<const float2*>(&g_ppart[z][p][c]);
        v0 += t.x; v1 += t.y;
    }
    v0 += bias[c];     v0 = v0 > 0.f ? v0 : 0.f;
    v1 += bias[c + 1]; v1 = v1 > 0.f ? v1 : 0.f;
    __nv_bfloat16 h0, h1, l0, l1;
    bsplit(v0, h0, l0); bsplit(v1, h1, l1);
    *reinterpret_cast<__nv_bfloat162*>(g_Ah + (size_t)p * D + c) = __nv_bfloat162(h0, h1);
    *reinterpret_cast<__nv_bfloat162*>(g_Al + (size_t)p * D + c) = __nv_bfloat162(l0, l1);
}

// ============================ launch ============================
extern "C" void kernel_launch(void* const* d_in, const int* in_sizes, int n_in,
                              void* d_out, int out_size) {
    const float* x    = (const float*)d_in[0];
    const float* prox = (const float*)d_in[1];
    const float* W1   = (const float*)d_in[2];
    const float* as1  = (const float*)d_in[3];
    const float* ad1  = (const float*)d_in[4];
    const float* b1   = (const float*)d_in[5];
    const float* W2   = (const float*)d_in[6];
    const float* as2  = (const float*)d_in[7];
    const float* ad2  = (const float*)d_in[8];
    const float* b2   = (const float*)d_in[9];
    const float* fcw  = (const float*)d_in[10];
    const float* fcb  = (const float*)d_in[11];
    float* out = (float*)d_out;

    __nv_bfloat16 *pAh, *pAl, *pW1h, *pW1l, *pW2h, *pW2l, *pFCh, *pFCl;
    cudaGetSymbolAddress((void**)&pAh,  g_Ah);
    cudaGetSymbolAddress((void**)&pAl,  g_Al);
    cudaGetSymbolAddress((void**)&pW1h, g_W1h);
    cudaGetSymbolAddress((void**)&pW1l, g_W1l);
    cudaGetSymbolAddress((void**)&pW2h, g_W2h);
    cudaGetSymbolAddress((void**)&pW2l, g_W2l);
    cudaGetSymbolAddress((void**)&pFCh, g_FCh);
    cudaGetSymbolAddress((void**)&pFCl, g_FCl);

    cudaFuncSetAttribute(k_mma,  cudaFuncAttributeMaxDynamicSharedMemorySize, 2 * STAGE_BYTES);
    cudaFuncSetAttribute(k_aggm, cudaFuncAttributeMaxDynamicSharedMemorySize, 2 * STAGE_BYTES);

    k_setup<<<1152, 256>>>(W1, W2, fcw, x, prox);

    // ---- layer 1
    k_mma<<<dim3(8, 18), 256, 2 * STAGE_BYTES>>>(pAh, pAl, pW1h, pW1l, nullptr, nullptr, 1, as1, ad1);
    k_alpha<<<256, 256>>>(1);
    k_aggm<<<128 + 16 * PSPLIT, 256, 2 * STAGE_BYTES>>>(b1, nullptr, 1);
    k_pfin<<<NP * D / 512, 256>>>(b1);

    // ---- layer 2 (proxy aggregation unused downstream)
    k_mma<<<dim3(8, 18), 256, 2 * STAGE_BYTES>>>(pAh, pAl, pW2h, pW2l, nullptr, nullptr, 1, as2, ad2);
    k_alpha<<<128, 256>>>(2);
    k_aggm<<<128, 256, 2 * STAGE_BYTES>>>(b2, out + NS * 100, 2);

    // ---- preds = h @ fc_w + fc_b
    k_mma<<<dim3(2, 16), 256, 2 * STAGE_BYTES>>>(pAh, pAl, pFCh, pFCl, out, fcb, 0, nullptr, nullptr);
}

// round 11
// speedup vs baseline: 1.3492x; 1.0272x over previous
#include <cuda_runtime.h>
#include <cuda_bf16.h>
#include <cstdint>

#define NP 100      // proxies
#define NS 1024     // samples
#define NN 1124     // total nodes
#define MPAD 1152   // NN padded to 128
#define D  512
#define KPAD2 128   // NP padded for sample-agg K
#define PSPLIT 9    // proxy-agg split-K factor (9 x 128 = 1152)

// scratch (device globals; no allocation allowed)
__device__ float g_HW[MPAD * D];
__device__ float g_aselfS[NS];
__device__ float g_lp[8][NN][2];        // logit partials [64col-tile][node][src/dst]
__device__ float g_ppart[PSPLIT][128][D];
// bf16 split operands
__device__ __nv_bfloat16 g_Ah[MPAD * D];
__device__ __nv_bfloat16 g_Al[MPAD * D];
__device__ __nv_bfloat16 g_W1h[D * D];
__device__ __nv_bfloat16 g_W1l[D * D];
__device__ __nv_bfloat16 g_W2h[D * D];
__device__ __nv_bfloat16 g_W2l[D * D];
__device__ __nv_bfloat16 g_FCh[128 * D];
__device__ __nv_bfloat16 g_FCl[128 * D];
__device__ __nv_bfloat16 g_Hth[D * MPAD];   // H transposed [d][node]
__device__ __nv_bfloat16 g_Htl[D * MPAD];
__device__ __nv_bfloat16 g_aSh[NS * KPAD2]; // alpha (sample dst), K-major
__device__ __nv_bfloat16 g_aSl[NS * KPAD2];
__device__ __nv_bfloat16 g_aPh[128 * MPAD]; // alpha (proxy dst), K over all nodes, self on diag
__device__ __nv_bfloat16 g_aPl[128 * MPAD];

__device__ __forceinline__ float lrelu(float v) { return v > 0.f ? v : 0.2f * v; }

__device__ __forceinline__ uint32_t smem_u32(const void* p) {
    uint32_t a;
    asm("{ .reg .u64 t; cvta.to.shared.u64 t, %1; cvt.u32.u64 %0, t; }" : "=r"(a) : "l"(p));
    return a;
}
__device__ __forceinline__ void bsplit(float v, __nv_bfloat16& hi, __nv_bfloat16& lo) {
    hi = __float2bfloat16(v);
    lo = __float2bfloat16(v - __bfloat162float(hi));
}

// ============================ setup: W splits + input convert ============================
__global__ void k_setup(const float* __restrict__ W1, const float* __restrict__ W2,
                        const float* __restrict__ fcw,
                        const float* __restrict__ x, const float* __restrict__ prox) {
    int b = blockIdx.x;
    if (b < 512) {
        const float* W = (b >= 256) ? W2 : W1;
        __nv_bfloat16* Wh = (b >= 256) ? g_W2h : g_W1h;
        __nv_bfloat16* Wl = (b >= 256) ? g_W2l : g_W1l;
        int bb = b & 255;
        __shared__ float t[32][33];
        int tx = threadIdx.x & 31, ty = threadIdx.x >> 5;
        int n0 = (bb & 15) * 32, k0 = (bb >> 4) * 32;
        #pragma unroll
        for (int j = 0; j < 4; j++)
            t[ty + 8 * j][tx] = W[(size_t)(k0 + ty + 8 * j) * D + n0 + tx];
        __syncthreads();
        #pragma unroll
        for (int j = 0; j < 4; j++) {
            int n = n0 + ty + 8 * j, k = k0 + tx;
            __nv_bfloat16 hi, lo;
            bsplit(t[tx][ty + 8 * j], hi, lo);
            Wh[(size_t)n * D + k] = hi;
            Wl[(size_t)n * D + k] = lo;
        }
    } else if (b < 576) {
        int bb = b - 512;
        __shared__ float t[32][33];
        int tx = threadIdx.x & 31, ty = threadIdx.x >> 5;
        int n0 = (bb & 3) * 32, k0 = (bb >> 2) * 32;
        #pragma unroll
        for (int j = 0; j < 4; j++) {
            int n = n0 + tx;
            t[ty + 8 * j][tx] = (n < 100) ? fcw[(size_t)(k0 + ty + 8 * j) * 100 + n] : 0.f;
        }
        __syncthreads();
        #pragma unroll
        for (int j = 0; j < 4; j++) {
            int n = n0 + ty + 8 * j, k = k0 + tx;
            __nv_bfloat16 hi, lo;
            bsplit(t[tx][ty + 8 * j], hi, lo);
            g_FCh[(size_t)n * D + k] = hi;
            g_FCl[(size_t)n * D + k] = lo;
        }
    } else {
        int row = (b - 576) * 2 + (threadIdx.x >> 7);
        int c4 = (threadIdx.x & 127) * 4;
        int base = row * D + c4;
        float4 v = make_float4(0.f, 0.f, 0.f, 0.f);
        if (row < NP)      v = *reinterpret_cast<const float4*>(prox + base);
        else if (row < NN) v = *reinterpret_cast<const float4*>(x + base - NP * D);
        __nv_bfloat16 h0, h1, h2, h3, l0, l1, l2, l3;
        bsplit(v.x, h0, l0); bsplit(v.y, h1, l1); bsplit(v.z, h2, l2); bsplit(v.w, h3, l3);
        *reinterpret_cast<__nv_bfloat162*>(g_Ah + base)     = __nv_bfloat162(h0, h1);
        *reinterpret_cast<__nv_bfloat162*>(g_Ah + base + 2) = __nv_bfloat162(h2, h3);
        *reinterpret_cast<__nv_bfloat162*>(g_Al + base)     = __nv_bfloat162(l0, l1);
        *reinterpret_cast<__nv_bfloat162*>(g_Al + base + 2) = __nv_bfloat162(l2, l3);
    }
}

// ============================ mma common ============================
#define SWB(r, b) ((r) * 128 + ((b) ^ (((r) & 7) << 4)))
#define STAGE_BYTES 32768

__device__ __forceinline__ void ldm_x4(uint32_t* f, uint32_t addr) {
    asm volatile("ldmatrix.sync.aligned.m8n8.x4.shared.b16 {%0,%1,%2,%3}, [%4];"
                 : "=r"(f[0]), "=r"(f[1]), "=r"(f[2]), "=r"(f[3]) : "r"(addr));
}
__device__ __forceinline__ void ldm_x2(uint32_t* f, uint32_t addr) {
    asm volatile("ldmatrix.sync.aligned.m8n8.x2.shared.b16 {%0,%1}, [%2];"
                 : "=r"(f[0]), "=r"(f[1]) : "r"(addr));
}
__device__ __forceinline__ void mma_bf16(float* c, const uint32_t* a, const uint32_t* b) {
    asm volatile(
        "mma.sync.aligned.m16n8k16.row.col.f32.bf16.bf16.f32 "
        "{%0,%1,%2,%3}, {%4,%5,%6,%7}, {%8,%9}, {%0,%1,%2,%3};"
        : "+f"(c[0]), "+f"(c[1]), "+f"(c[2]), "+f"(c[3])
        : "r"(a[0]), "r"(a[1]), "r"(a[2]), "r"(a[3]), "r"(b[0]), "r"(b[1]));
}
__device__ __forceinline__ void cpa16(uint32_t saddr, const void* g) {
    asm volatile("cp.async.cg.shared.global [%0], [%1], 16;" :: "r"(saddr), "l"(g));
}

#define MMA_MAINLOOP(AH, AL, BH, BL, LDA, LDB, NCHUNK, KOFF)                             \
    int li = tid * 2;                                                                    \
    int lr0 = li >> 3, ls0 = li & 7;                                                     \
    int lr1 = (li + 1) >> 3, ls1 = (li + 1) & 7;                                         \
    int a_r = (lane & 7) + ((lane >> 3) & 1) * 8;                                        \
    int a_kb = (lane >> 4) * 16;                                                         \
    int b_r = lane & 7;                                                                  \
    int b_kb = ((lane >> 3) & 1) * 16;                                                   \
    float acc[2][2][4] = {};                                                             \
    auto issue = [&](int c, int st) {                                                    \
        int kc = (KOFF) + c * 64;                                                        \
        uint32_t stb = sb + st * STAGE_BYTES;                                            \
        cpa16(stb + SWB(lr0, ls0 * 16), (AH) + (size_t)(m0 + lr0) * (LDA) + kc + ls0 * 8); \
        cpa16(stb + SWB(lr1, ls1 * 16), (AH) + (size_t)(m0 + lr1) * (LDA) + kc + ls1 * 8); \
        cpa16(stb + 8192 + SWB(lr0, ls0 * 16), (AL) + (size_t)(m0 + lr0) * (LDA) + kc + ls0 * 8); \
        cpa16(stb + 8192 + SWB(lr1, ls1 * 16), (AL) + (size_t)(m0 + lr1) * (LDA) + kc + ls1 * 8); \
        cpa16(stb + 16384 + SWB(lr0, ls0 * 16), (BH) + (size_t)(n0 + lr0) * (LDB) + kc + ls0 * 8); \
        cpa16(stb + 16384 + SWB(lr1, ls1 * 16), (BH) + (size_t)(n0 + lr1) * (LDB) + kc + ls1 * 8); \
        cpa16(stb + 24576 + SWB(lr0, ls0 * 16), (BL) + (size_t)(n0 + lr0) * (LDB) + kc + ls0 * 8); \
        cpa16(stb + 24576 + SWB(lr1, ls1 * 16), (BL) + (size_t)(n0 + lr1) * (LDB) + kc + ls1 * 8); \
        asm volatile("cp.async.commit_group;");                                          \
    };                                                                                   \
    issue(0, 0);                                                                         \
    asm volatile("cp.async.wait_group 0;");                                              \
    __syncthreads();                                                                     \
    for (int c = 0; c < (NCHUNK); c++) {                                                 \
        int st = c & 1;                                                                  \
        if (c + 1 < (NCHUNK)) issue(c + 1, st ^ 1);                                      \
        uint32_t stb = sb + st * STAGE_BYTES;                                            \
        _Pragma("unroll")                                                                \
        for (int ks = 0; ks < 4; ks++) {                                                 \
            int kb = ks * 32;                                                            \
            uint32_t ah[2][4], al[2][4], bh[2][2], bl[2][2];                             \
            _Pragma("unroll")                                                            \
            for (int mt = 0; mt < 2; mt++) {                                             \
                int r = wm + mt * 16 + a_r;                                              \
                ldm_x4(ah[mt], stb + 0    + SWB(r, kb + a_kb));                          \
                ldm_x4(al[mt], stb + 8192 + SWB(r, kb + a_kb));                          \
            }                                                                            \
            _Pragma("unroll")                                                            \
            for (int nt = 0; nt < 2; nt++) {                                             \
                int r = wn + nt * 8 + b_r;                                               \
                ldm_x2(bh[nt], stb + 16384 + SWB(r, kb + b_kb));                         \
                ldm_x2(bl[nt], stb + 24576 + SWB(r, kb + b_kb));                         \
            }                                                                            \
            _Pragma("unroll")                                                            \
            for (int mt = 0; mt < 2; mt++)                                               \
                _Pragma("unroll")                                                        \
                for (int nt = 0; nt < 2; nt++) {                                         \
                    mma_bf16(acc[mt][nt], ah[mt], bh[nt]);                               \
                    mma_bf16(acc[mt][nt], ah[mt], bl[nt]);                               \
                    mma_bf16(acc[mt][nt], al[mt], bh[nt]);                               \
                }                                                                        \
        }                                                                                \
        if (c + 1 < (NCHUNK)) asm volatile("cp.async.wait_group 0;");                    \
        __syncthreads();                                                                 \
    }

// ============================ layer GEMM / FC GEMM ============================
// mode 0: FC -> C fp32 (ldc=100, col guard) + bias.
// mode 1: H = A@W -> g_HW fp32 + g_lp logit partials + Ht bf16 split.
__global__ void __launch_bounds__(256, 2) k_mma(
    const __nv_bfloat16* __restrict__ Ah, const __nv_bfloat16* __restrict__ Al,
    const __nv_bfloat16* __restrict__ Bh, const __nv_bfloat16* __restrict__ Bl,
    float* __restrict__ C, const float* __restrict__ bias, int mode,
    const float* __restrict__ asrc, const float* __restrict__ adst) {
    extern __shared__ __align__(16) char sm[];
    int tid = threadIdx.x, wid = tid >> 5, lane = tid & 31;
    int n0 = blockIdx.x * 64, m0 = blockIdx.y * 64;
    int wm = (wid >> 2) * 32, wn = (wid & 3) * 16;
    uint32_t sb = smem_u32(sm);

    MMA_MAINLOOP(Ah, Al, Bh, Bl, D, D, 8, 0)

    if (mode == 0) {
        #pragma unroll
        for (int mt = 0; mt < 2; mt++) {
            int row = m0 + wm + mt * 16 + (lane >> 2);
            #pragma unroll
            for (int nt = 0; nt < 2; nt++) {
                int col = n0 + wn + nt * 8 + (lane & 3) * 2;
                if (col >= 100) continue;
                float b0 = bias[col], b1 = bias[col + 1];
                *reinterpret_cast<float2*>(C + (size_t)row * 100 + col) =
                    make_float2(acc[mt][nt][0] + b0, acc[mt][nt][1] + b1);
                *reinterpret_cast<float2*>(C + (size_t)(row + 8) * 100 + col) =
                    make_float2(acc[mt][nt][2] + b0, acc[mt][nt][3] + b1);
            }
        }
        return;
    }

    // fp32 HW store
    #pragma unroll
    for (int mt = 0; mt < 2; mt++) {
        int row = m0 + wm + mt * 16 + (lane >> 2);
        #pragma unroll
        for (int nt = 0; nt < 2; nt++) {
            int col = n0 + wn + nt * 8 + (lane & 3) * 2;
            *reinterpret_cast<float2*>(g_HW + (size_t)row * D + col) =
                make_float2(acc[mt][nt][0], acc[mt][nt][1]);
            *reinterpret_cast<float2*>(g_HW + (size_t)(row + 8) * D + col) =
                make_float2(acc[mt][nt][2], acc[mt][nt][3]);
        }
    }

    // logit partials
    {
        float* lpb = reinterpret_cast<float*>(sm);   // [64][4][2]
        #pragma unroll
        for (int mt = 0; mt < 2; mt++)
            #pragma unroll
            for (int half = 0; half < 2; half++) {
                int rl = wm + mt * 16 + (lane >> 2) + half * 8;
                float s = 0.f, t = 0.f;
                #pragma unroll
                for (int nt = 0; nt < 2; nt++) {
                    int col = n0 + wn + nt * 8 + (lane & 3) * 2;
                    float v0 = acc[mt][nt][half * 2], v1 = acc[mt][nt][half * 2 + 1];
                    s += v0 * asrc[col] + v1 * asrc[col + 1];
                    t += v0 * adst[col] + v1 * adst[col + 1];
                }
                s += __shfl_xor_sync(0xffffffffu, s, 1);
                s += __shfl_xor_sync(0xffffffffu, s, 2);
                t += __shfl_xor_sync(0xffffffffu, t, 1);
                t += __shfl_xor_sync(0xffffffffu, t, 2);
                if ((lane & 3) == 0) {
                    lpb[(rl * 4 + (wid & 3)) * 2 + 0] = s;
                    lpb[(rl * 4 + (wid & 3)) * 2 + 1] = t;
                }
            }
        __syncthreads();
        if (tid < 128) {
            int rl = tid >> 1, comp = tid & 1;
            int row = m0 + rl;
            if (row < NN) {
                float s = lpb[(rl * 4 + 0) * 2 + comp] + lpb[(rl * 4 + 1) * 2 + comp]
                        + lpb[(rl * 4 + 2) * 2 + comp] + lpb[(rl * 4 + 3) * 2 + comp];
                g_lp[n0 >> 6][row][comp] = s;
            }
        }
        __syncthreads();
    }

    // transpose via smem, write Ht bf16 split
    float* ts = reinterpret_cast<float*>(sm);   // [64][65]
    #pragma unroll
    for (int mt = 0; mt < 2; mt++)
        #pragma unroll
        for (int nt = 0; nt < 2; nt++)
            #pragma unroll
            for (int j = 0; j < 4; j++) {
                int rl = wm + mt * 16 + (lane >> 2) + (j >> 1) * 8;
                int cl = wn + nt * 8 + (lane & 3) * 2 + (j & 1);
                ts[rl * 65 + cl] = acc[mt][nt][j];
            }
    __syncthreads();
    #pragma unroll
    for (int it = 0; it < 16; it++) {
        int lin = it * 256 + tid;
        int n = lin >> 6, m = lin & 63;
        __nv_bfloat16 hi, lo;
        bsplit(ts[m * 65 + n], hi, lo);
        g_Hth[(size_t)(n0 + n) * MPAD + m0 + m] = hi;
        g_Htl[(size_t)(n0 + n) * MPAD + m0 + m] = lo;
    }
}

// ============================ alpha (from g_lp; no max subtraction) ============================
__global__ void k_alpha(int layer) {
    int tid = threadIdx.x;
    int b = blockIdx.x;
    if (b < 128) {
        __shared__ float lsp[128];
        if (tid < NP) {
            float s = 0.f;
            #pragma unroll
            for (int ti = 0; ti < 8; ti++) s += g_lp[ti][tid][0];
            lsp[tid] = s;
        }
        __syncthreads();
        int warp = b * 8 + (tid >> 5);
        int lane = tid & 31;
        int node = NP + warp;
        float lsn = 0.f, ldn = 0.f;
        #pragma unroll
        for (int ti = 0; ti < 8; ti++) {
            lsn += g_lp[ti][node][0];
            ldn += g_lp[ti][node][1];
        }
        float w[4], sum = 0.f;
        #pragma unroll
        for (int i = 0; i < 4; i++) {
            int p = lane + 32 * i;
            w[i] = (p < NP) ? __expf(lrelu(lsp[p] + ldn)) : 0.f;
            sum += w[i];
        }
        float wself = __expf(lrelu(lsn + ldn));
        #pragma unroll
        for (int o = 16; o > 0; o >>= 1) sum += __shfl_xor_sync(0xffffffffu, sum, o);
        float inv = 1.f / (sum + wself);
        #pragma unroll
        for (int i = 0; i < 4; i++) {
            int p = lane + 32 * i;
            __nv_bfloat16 hi, lo;
            bsplit(w[i] * inv, hi, lo);
            g_aSh[(size_t)warp * KPAD2 + p] = hi;
            g_aSl[(size_t)warp * KPAD2 + p] = lo;
        }
        if (lane == 0) g_aselfS[warp] = wself * inv;
    } else if (b < 228) {
        __shared__ float sh[8];
        __shared__ float s_inv;
        int p = b - 128;
        float ldp = 0.f, lspp = 0.f;
        #pragma unroll
        for (int ti = 0; ti < 8; ti++) {
            ldp += g_lp[ti][p][1];
            lspp += g_lp[ti][p][0];
        }
        float w[4], sum = 0.f;
        #pragma unroll
        for (int i = 0; i < 4; i++) {
            int s = tid + i * 256;
            float ls = 0.f;
            #pragma unroll
            for (int ti = 0; ti < 8; ti++) ls += g_lp[ti][NP + s][0];
            w[i] = __expf(lrelu(ls + ldp));
            sum += w[i];
        }
        float wself = __expf(lrelu(lspp + ldp));
        #pragma unroll
        for (int o = 16; o > 0; o >>= 1) sum += __shfl_xor_sync(0xffffffffu, sum, o);
        if ((tid & 31) == 0) sh[tid >> 5] = sum;
        __syncthreads();
        if (tid == 0) {
            float ss = 0.f;
            #pragma unroll
            for (int i = 0; i < 8; i++) ss += sh[i];
            s_inv = 1.f / (ss + wself);
        }
        __syncthreads();
        float inv = s_inv;
        #pragma unroll
        for (int i = 0; i < 4; i++) {
            int col = NP + tid + i * 256;
            __nv_bfloat16 hi, lo;
            bsplit(w[i] * inv, hi, lo);
            g_aPh[(size_t)p * MPAD + col] = hi;
            g_aPl[(size_t)p * MPAD + col] = lo;
        }
        if (tid < NP) {
            float dv = (tid == p) ? wself * inv : 0.f;
            __nv_bfloat16 hi, lo;
            bsplit(dv, hi, lo);
            g_aPh[(size_t)p * MPAD + tid] = hi;
            g_aPl[(size_t)p * MPAD + tid] = lo;
        }
        if (tid < MPAD - NN) {
            __nv_bfloat16 z = __float2bfloat16(0.f);
            g_aPh[(size_t)p * MPAD + NN + tid] = z;
            g_aPl[(size_t)p * MPAD + NN + tid] = z;
        }
    } else {
        int p = 100 + (b - 228);
        uint32_t* h = reinterpret_cast<uint32_t*>(g_aPh + (size_t)p * MPAD);
        uint32_t* l = reinterpret_cast<uint32_t*>(g_aPl + (size_t)p * MPAD);
        for (int i = tid; i < MPAD / 2; i += 256) { h[i] = 0u; l[i] = 0u; }
    }
}

// ============================ aggregation GEMM (tensor cores) ============================
// blocks 0..127 sample tiles (K=128).
// layer 1 only: blocks 128..271 proxy tiles x split-K (16 tiles x 9 splits, 2 chunks each).
__global__ void __launch_bounds__(256, 2) k_aggm(const float* __restrict__ bias,
                                                 float* __restrict__ hout, int layer) {
    extern __shared__ __align__(16) char sm[];
    int tid = threadIdx.x, wid = tid >> 5, lane = tid & 31;
    int wm = (wid >> 2) * 32, wn = (wid & 3) * 16;
    uint32_t sb = smem_u32(sm);
    int b = blockIdx.x;

    if (b < 128) {
        int m0 = (b >> 3) * 64, n0 = (b & 7) * 64;
        MMA_MAINLOOP(g_aSh, g_aSl, g_Hth, g_Htl, KPAD2, MPAD, 2, 0)
        #pragma unroll
        for (int mt = 0; mt < 2; mt++)
            #pragma unroll
            for (int nt = 0; nt < 2; nt++)
                #pragma unroll
                for (int j = 0; j < 4; j++) {
                    int r = m0 + wm + mt * 16 + (lane >> 2) + (j >> 1) * 8;
                    int col = n0 + wn + nt * 8 + (lane & 3) * 2 + (j & 1);
                    float v = acc[mt][nt][j] + g_aselfS[r] * g_HW[(size_t)(NP + r) * D + col]
                            + bias[col];
                    acc[mt][nt][j] = v > 0.f ? v : 0.f;
                }
        #pragma unroll
        for (int mt = 0; mt < 2; mt++)
            #pragma unroll
            for (int half = 0; half < 2; half++) {
                int r = m0 + wm + mt * 16 + (lane >> 2) + half * 8;
                int arow = (layer == 1) ? (NP + r) : r;
                #pragma unroll
                for (int nt = 0; nt < 2; nt++) {
                    int col = n0 + wn + nt * 8 + (lane & 3) * 2;
                    float v0 = acc[mt][nt][half * 2], v1 = acc[mt][nt][half * 2 + 1];
                    __nv_bfloat16 h0, h1, l0, l1;
                    bsplit(v0, h0, l0); bsplit(v1, h1, l1);
                    *reinterpret_cast<__nv_bfloat162*>(g_Ah + (size_t)arow * D + col) =
                        __nv_bfloat162(h0, h1);
                    *reinterpret_cast<__nv_bfloat162*>(g_Al + (size_t)arow * D + col) =
                        __nv_bfloat162(l0, l1);
                    if (layer == 2)
                        *reinterpret_cast<float2*>(hout + (size_t)r * D + col) =
                            make_float2(v0, v1);
                }
            }
    } else {
        int bb = b - 128;
        int tile = bb & 15;
        int z = bb >> 4;                       // split index 0..8
        int m0 = (tile >> 3) * 64, n0 = (tile & 7) * 64;
        MMA_MAINLOOP(g_aPh, g_aPl, g_Hth, g_Htl, MPAD, MPAD, 2, z * 128)
        float* part = &g_ppart[z][0][0];
        #pragma unroll
        for (int mt = 0; mt < 2; mt++)
            #pragma unroll
            for (int half = 0; half < 2; half++) {
                int p = m0 + wm + mt * 16 + (lane >> 2) + half * 8;
                if (p >= NP) continue;
                #pragma unroll
                for (int nt = 0; nt < 2; nt++) {
                    int col = n0 + wn + nt * 8 + (lane & 3) * 2;
                    *reinterpret_cast<float2*>(part + (size_t)p * D + col) =
                        make_float2(acc[mt][nt][half * 2], acc[mt][nt][half * 2 + 1]);
                }
            }
    }
}

// proxy finalize: sum 9 split-K partials + bias, relu -> bf16 split rows 0..99 of g_Ah/g_Al
__global__ void k_pfin(const float* __restrict__ bias) {
    int idx = blockIdx.x * 256 + threadIdx.x;   // over NP*D/2 float2 elems
    int p = idx / (D / 2);
    int c = (idx - p * (D / 2)) * 2;
    float v0 = 0.f, v1 = 0.f;
    #pragma unroll
    for (int z = 0; z < PSPLIT; z++) {
        float2 t = *reinterpret_cast<const float2*>(&g_ppart[z][p][c]);
        v0 += t.x; v1 += t.y;
    }
    v0 += bias[c];     v0 = v0 > 0.f ? v0 : 0.f;
    v1 += bias[c + 1]; v1 = v1 > 0.f ? v1 : 0.f;
    __nv_bfloat16 h0, h1, l0, l1;
    bsplit(v0, h0, l0); bsplit(v1, h1, l1);
    *reinterpret_cast<__nv_bfloat162*>(g_Ah + (size_t)p * D + c) = __nv_bfloat162(h0, h1);
    *reinterpret_cast<__nv_bfloat162*>(g_Al + (size_t)p * D + c) = __nv_bfloat162(l0, l1);
}

// ============================ launch ============================
extern "C" void kernel_launch(void* const* d_in, const int* in_sizes, int n_in,
                              void* d_out, int out_size) {
    const float* x    = (const float*)d_in[0];
    const float* prox = (const float*)d_in[1];
    const float* W1   = (const float*)d_in[2];
    const float* as1  = (const float*)d_in[3];
    const float* ad1  = (const float*)d_in[4];
    const float* b1   = (const float*)d_in[5];
    const float* W2   = (const float*)d_in[6];
    const float* as2  = (const float*)d_in[7];
    const float* ad2  = (const float*)d_in[8];
    const float* b2   = (const float*)d_in[9];
    const float* fcw  = (const float*)d_in[10];
    const float* fcb  = (const float*)d_in[11];
    float* out = (float*)d_out;

    __nv_bfloat16 *pAh, *pAl, *pW1h, *pW1l, *pW2h, *pW2l, *pFCh, *pFCl;
    cudaGetSymbolAddress((void**)&pAh,  g_Ah);
    cudaGetSymbolAddress((void**)&pAl,  g_Al);
    cudaGetSymbolAddress((void**)&pW1h, g_W1h);
    cudaGetSymbolAddress((void**)&pW1l, g_W1l);
    cudaGetSymbolAddress((void**)&pW2h, g_W2h);
    cudaGetSymbolAddress((void**)&pW2l, g_W2l);
    cudaGetSymbolAddress((void**)&pFCh, g_FCh);
    cudaGetSymbolAddress((void**)&pFCl, g_FCl);

    cudaFuncSetAttribute(k_mma,  cudaFuncAttributeMaxDynamicSharedMemorySize, 2 * STAGE_BYTES);
    cudaFuncSetAttribute(k_aggm, cudaFuncAttributeMaxDynamicSharedMemorySize, 2 * STAGE_BYTES);

    k_setup<<<1152, 256>>>(W1, W2, fcw, x, prox);

    // ---- layer 1
    k_mma<<<dim3(8, 18), 256, 2 * STAGE_BYTES>>>(pAh, pAl, pW1h, pW1l, nullptr, nullptr, 1, as1, ad1);
    k_alpha<<<256, 256>>>(1);
    k_aggm<<<128 + 16 * PSPLIT, 256, 2 * STAGE_BYTES>>>(b1, nullptr, 1);
    k_pfin<<<NP * D / 512, 256>>>(b1);

    // ---- layer 2 (proxy aggregation unused downstream)
    k_mma<<<dim3(8, 18), 256, 2 * STAGE_BYTES>>>(pAh, pAl, pW2h, pW2l, nullptr, nullptr, 1, as2, ad2);
    k_alpha<<<128, 256>>>(2);
    k_aggm<<<128, 256, 2 * STAGE_BYTES>>>(b2, out + NS * 100, 2);

    // ---- preds = h @ fc_w + fc_b
    k_mma<<<dim3(2, 16), 256, 2 * STAGE_BYTES>>>(pAh, pAl, pFCh, pFCl, out, fcb, 0, nullptr, nullptr);
}